// round 11
// baseline (speedup 1.0000x reference)
#include <cuda_runtime.h>
#include <cuda_bf16.h>
#include <math.h>
#include <stdint.h>

#define BB 4
#define CC 1024
#define TT 4096
#define HH 16
#define DD 64
#define BT (BB*TT)        // 16384
#define KSPLIT 8
#define NKCH 32           // K chunks of 32 per proj GEMM
#define SA 40             // GEMM smem row stride (bf16) — conflict-free for ldmatrix

// ---------------- scratch (alloc-free: __device__ globals) ----------------
__device__ __nv_bfloat16 g_xt [(size_t)BT*CC];     // xt[bt][c]
__device__ __nv_bfloat16 g_q16[(size_t)BT*CC];     // q[bt][c]
__device__ __nv_bfloat16 g_kt [(size_t)BB*CC*TT];  // k^T[b*CC+c][t]
__device__ __nv_bfloat16 g_vt [(size_t)BB*CC*TT];  // v^T[b*CC+c][t]
__device__ __nv_bfloat16 g_attn16[(size_t)BT*CC];  // attn[bt][c]
__device__ __nv_bfloat16 g_w16[(size_t)4*CC*CC];   // Wq,Wk,Wv,Wo bf16
// kv partials: [split][bh][n(72: 0..63=kv cols e, 64=ksum)][d(64)]
__device__ float g_kvP[KSPLIT][BB*HH][72*64];
__device__ __nv_bfloat16 g_kv16[(size_t)BB*HH*72*64];   // reduced kv, bf16

// ---------------- helpers ----------------
__device__ __forceinline__ uint32_t smem_u32(const void* p){
    uint32_t a;
    asm("{ .reg .u64 t; cvta.to.shared.u64 t, %1; cvt.u32.u64 %0, t; }" : "=r"(a) : "l"(p));
    return a;
}

#define CP_ASYNC16(saddr, gptr) \
    asm volatile("cp.async.cg.shared.global [%0], [%1], 16;" :: "r"(saddr), "l"(gptr))
#define CP_COMMIT() asm volatile("cp.async.commit_group;" ::: "memory")
#define CP_WAIT1()  asm volatile("cp.async.wait_group 1;" ::: "memory")
#define CP_WAIT0()  asm volatile("cp.async.wait_group 0;" ::: "memory")

// m16n8k16 bf16: D += A(16x16,row) * B(16x8, stored [n][k], k contiguous)
__device__ __forceinline__ void mma_bf16(float* c, const uint32_t* a, const uint32_t* b){
    asm volatile("mma.sync.aligned.m16n8k16.row.col.f32.bf16.bf16.f32 "
        "{%0,%1,%2,%3}, {%4,%5,%6,%7}, {%8,%9}, {%0,%1,%2,%3};"
        : "+f"(c[0]), "+f"(c[1]), "+f"(c[2]), "+f"(c[3])
        : "r"(a[0]), "r"(a[1]), "r"(a[2]), "r"(a[3]), "r"(b[0]), "r"(b[1]));
}
__device__ __forceinline__ uint32_t lds32(const __nv_bfloat16* p){
    return *reinterpret_cast<const uint32_t*>(p);
}
__device__ __forceinline__ void ldsm_x4(uint32_t* r, uint32_t addr){
    asm volatile("ldmatrix.sync.aligned.m8n8.x4.shared.b16 {%0,%1,%2,%3}, [%4];"
        : "=r"(r[0]), "=r"(r[1]), "=r"(r[2]), "=r"(r[3]) : "r"(addr));
}

#define STG (128*SA)                 // bf16 elements per operand per stage
#define GEMM_SMEM (3*2*STG*2)        // bytes = 61440

// ---------------------------------------------------------------------------
// GEMM core (proven): block 128x128, 8 warps (4m x 2n), warp tile 32x64,
// 3-stage cp.async, ldmatrix.
// ---------------------------------------------------------------------------
struct GemmCtx {
    int tid, wid, lane, g, t4, wm, wn;
};

__device__ __forceinline__ void gemm_core(
    const __nv_bfloat16* __restrict__ Ab, const __nv_bfloat16* __restrict__ Bb,
    uint32_t su, const GemmCtx& c, float acc[2][8][4])
{
    const int rowA_l = (c.lane & 7) + 8*((c.lane >> 3) & 1);
    const int colA_l = 8*(c.lane >> 4);
    const int rowB_l = (c.lane & 7) + 8*(c.lane >> 4);
    const int colB_l = 8*((c.lane >> 3) & 1);

    auto load_stage = [&](int st, int kc){
        const uint32_t sa = su + (uint32_t)(st*2*STG)*2;
        const uint32_t sb = sa + (uint32_t)STG*2;
        const __nv_bfloat16* a = Ab + kc*32;
        const __nv_bfloat16* b = Bb + kc*32;
        #pragma unroll
        for (int r = 0; r < 2; r++){
            int i = c.tid + r*256;
            int row = i >> 2, cq = i & 3;
            CP_ASYNC16(sa + (uint32_t)(row*SA + cq*8)*2, a + (size_t)row*CC + cq*8);
            CP_ASYNC16(sb + (uint32_t)(row*SA + cq*8)*2, b + (size_t)row*CC + cq*8);
        }
        CP_COMMIT();
    };

    load_stage(0, 0);
    load_stage(1, 1);

    for (int kc = 0; kc < NKCH; kc++){
        if (kc + 1 < NKCH) { CP_WAIT1(); } else { CP_WAIT0(); }
        __syncthreads();
        if (kc + 2 < NKCH) load_stage((kc+2) % 3, kc+2);

        const int st = kc % 3;
        const uint32_t sa = su + (uint32_t)(st*2*STG)*2;
        const uint32_t sb = sa + (uint32_t)STG*2;
        #pragma unroll
        for (int s = 0; s < 2; s++){
            const int sk = s*16;
            uint32_t ar[2][4], br[4][4];
            #pragma unroll
            for (int mf = 0; mf < 2; mf++){
                int ml = c.wm*32 + mf*16;
                ldsm_x4(ar[mf], sa + (uint32_t)((ml + rowA_l)*SA + sk + colA_l)*2);
            }
            #pragma unroll
            for (int nf2 = 0; nf2 < 4; nf2++){
                int nl = c.wn*64 + nf2*16;
                ldsm_x4(br[nf2], sb + (uint32_t)((nl + rowB_l)*SA + sk + colB_l)*2);
            }
            #pragma unroll
            for (int mf = 0; mf < 2; mf++)
                #pragma unroll
                for (int nf = 0; nf < 8; nf++)
                    mma_bf16(acc[mf][nf], ar[mf], &br[nf >> 1][(nf & 1)*2]);
        }
    }
}

// ---------------------------------------------------------------------------
// Q/K/V projection. z = blockIdx.x + zoff: 0=Q (row-major), 1=K (transposed,
// elu+1), 2=V (transposed). Launched as (2,...) zoff=1 for K,V and (1,...)
// zoff=0 for Q so kv_mma can overlap the Q GEMM on a second stream.
// ---------------------------------------------------------------------------
__global__ void __launch_bounds__(256, 2)
gemm_qkv(const __nv_bfloat16* __restrict__ A, const __nv_bfloat16* __restrict__ W,
         const float* __restrict__ bq, const float* __restrict__ bk,
         const float* __restrict__ bv,
         __nv_bfloat16* __restrict__ outq, __nv_bfloat16* __restrict__ outkt,
         __nv_bfloat16* __restrict__ outvt, int zoff)
{
    extern __shared__ __nv_bfloat16 sm[];
    const uint32_t su = smem_u32(sm);
    GemmCtx c;
    c.tid = threadIdx.x; c.wid = c.tid >> 5; c.lane = c.tid & 31;
    c.g = c.lane >> 2; c.t4 = c.lane & 3;
    c.wm = c.wid >> 1;  c.wn = c.wid & 1;
    const int z  = blockIdx.x + zoff;
    const int bm = blockIdx.y * 128;
    const int bn = blockIdx.z * 128;

    const float* bias = (z == 0) ? bq : (z == 1) ? bk : bv;
    const __nv_bfloat16* Ab = A + (size_t)bm * CC;
    const __nv_bfloat16* Bb = W + (size_t)z*CC*CC + (size_t)bn * CC;

    float acc[2][8][4];
    #pragma unroll
    for (int i = 0; i < 2; i++)
        #pragma unroll
        for (int j = 0; j < 8; j++)
            #pragma unroll
            for (int e = 0; e < 4; e++) acc[i][j][e] = 0.f;

    gemm_core(Ab, Bb, su, c, acc);

    const bool act = (z != 2);
    #pragma unroll
    for (int mf = 0; mf < 2; mf++){
        const int m0 = bm + c.wm*32 + mf*16 + c.g;
        #pragma unroll
        for (int nf = 0; nf < 8; nf++){
            const int n0 = bn + c.wn*64 + nf*8 + c.t4*2;
            const float b0 = bias[n0], b1 = bias[n0+1];
            float v00 = acc[mf][nf][0] + b0;
            float v01 = acc[mf][nf][1] + b1;
            float v10 = acc[mf][nf][2] + b0;
            float v11 = acc[mf][nf][3] + b1;
            if (act){
                v00 = (v00 > 0.f) ? (v00 + 1.f) : expf(v00);
                v01 = (v01 > 0.f) ? (v01 + 1.f) : expf(v01);
                v10 = (v10 > 0.f) ? (v10 + 1.f) : expf(v10);
                v11 = (v11 > 0.f) ? (v11 + 1.f) : expf(v11);
            }
            if (z == 0){
                *reinterpret_cast<__nv_bfloat162*>(outq + (size_t) m0   *CC + n0)
                    = __floats2bfloat162_rn(v00, v01);
                *reinterpret_cast<__nv_bfloat162*>(outq + (size_t)(m0+8)*CC + n0)
                    = __floats2bfloat162_rn(v10, v11);
            } else {
                __nv_bfloat16* o = (z == 1) ? outkt : outvt;
                const int b = m0 / TT, t = m0 % TT;
                size_t r0i = ((size_t)b*CC + n0)*TT + t;
                size_t r1i = r0i + TT;
                o[r0i]     = __float2bfloat16_rn(v00);
                o[r1i]     = __float2bfloat16_rn(v01);
                o[r0i + 8] = __float2bfloat16_rn(v10);
                o[r1i + 8] = __float2bfloat16_rn(v11);
            }
        }
    }
}

// ---------------------------------------------------------------------------
// Output projection + bias + residual + transpose -> fp32 out[b][n][t]
// Grid = (CC/128, BT/128): n FASTEST so blocks sharing an A tile co-run.
// ---------------------------------------------------------------------------
__global__ void __launch_bounds__(256, 2)
gemm_out(const __nv_bfloat16* __restrict__ A, const __nv_bfloat16* __restrict__ W,
         const float* __restrict__ bias, const float* __restrict__ resid,
         float* __restrict__ outf)
{
    extern __shared__ __nv_bfloat16 sm[];
    const uint32_t su = smem_u32(sm);
    GemmCtx c;
    c.tid = threadIdx.x; c.wid = c.tid >> 5; c.lane = c.tid & 31;
    c.g = c.lane >> 2; c.t4 = c.lane & 3;
    c.wm = c.wid >> 1;  c.wn = c.wid & 1;
    const int bn = blockIdx.x * 128;
    const int bm = blockIdx.y * 128;

    const __nv_bfloat16* Ab = A + (size_t)bm * CC;
    const __nv_bfloat16* Bb = W + (size_t)bn * CC;

    float acc[2][8][4];
    #pragma unroll
    for (int i = 0; i < 2; i++)
        #pragma unroll
        for (int j = 0; j < 8; j++)
            #pragma unroll
            for (int e = 0; e < 4; e++) acc[i][j][e] = 0.f;

    gemm_core(Ab, Bb, su, c, acc);

    #pragma unroll
    for (int mf = 0; mf < 2; mf++){
        const int m0 = bm + c.wm*32 + mf*16 + c.g;
        const int b = m0 / TT, t = m0 % TT;
        #pragma unroll
        for (int nf = 0; nf < 8; nf++){
            const int n0 = bn + c.wn*64 + nf*8 + c.t4*2;
            size_t i00 = (size_t)b*CC*TT + (size_t)n0*TT + t;
            size_t i01 = i00 + TT;
            outf[i00]     = acc[mf][nf][0] + bias[n0]   + resid[i00];
            outf[i01]     = acc[mf][nf][1] + bias[n0+1] + resid[i01];
            outf[i00 + 8] = acc[mf][nf][2] + bias[n0]   + resid[i00 + 8];
            outf[i01 + 8] = acc[mf][nf][3] + bias[n0+1] + resid[i01 + 8];
        }
    }
}

// ---------------------------------------------------------------------------
// x[b,c,t] -> g_xt[b*T+t][c] bf16. 64x64 tiles, float4 loads, uint4 stores.
// ---------------------------------------------------------------------------
__global__ void __launch_bounds__(256) transpose_round_kernel(const float* __restrict__ x)
{
    __shared__ float tile[64][65];
    const int t0 = blockIdx.x * 64;
    const int c0 = blockIdx.y * 64;
    const int b  = blockIdx.z;
    const int tid = threadIdx.x;
    const int row = tid >> 2;            // c-row within tile
    const int q   = tid & 3;

    const float* src = x + (size_t)b*CC*TT + (size_t)(c0+row)*TT + t0 + q*16;
    #pragma unroll
    for (int j = 0; j < 4; j++){
        float4 v = *reinterpret_cast<const float4*>(src + j*4);
        tile[row][q*16 + j*4 + 0] = v.x;
        tile[row][q*16 + j*4 + 1] = v.y;
        tile[row][q*16 + j*4 + 2] = v.z;
        tile[row][q*16 + j*4 + 3] = v.w;
    }
    __syncthreads();

    uint32_t* dst = reinterpret_cast<uint32_t*>(
        g_xt + (size_t)(b*TT + t0 + row)*CC + c0);
    uint32_t tmp[8];
    #pragma unroll
    for (int j = 0; j < 8; j++){
        int cu = q*8 + j;                 // u32 column
        __nv_bfloat162 p = __floats2bfloat162_rn(tile[2*cu][row], tile[2*cu+1][row]);
        tmp[j] = *reinterpret_cast<uint32_t*>(&p);
    }
    *reinterpret_cast<uint4*>(dst + q*8)     = make_uint4(tmp[0], tmp[1], tmp[2], tmp[3]);
    *reinterpret_cast<uint4*>(dst + q*8 + 4) = make_uint4(tmp[4], tmp[5], tmp[6], tmp[7]);
}

// all 4 weights in one launch, vectorized x4: blockIdx.y selects the matrix
__global__ void round_w4_kernel(const float* __restrict__ w0, const float* __restrict__ w1,
                                const float* __restrict__ w2, const float* __restrict__ w3,
                                __nv_bfloat16* __restrict__ dst)
{
    const float* w = (blockIdx.y == 0) ? w0 : (blockIdx.y == 1) ? w1
                   : (blockIdx.y == 2) ? w2 : w3;
    int i = (blockIdx.x * 256 + threadIdx.x) * 4;
    float4 v = *reinterpret_cast<const float4*>(w + i);
    __nv_bfloat162 lo = __floats2bfloat162_rn(v.x, v.y);
    __nv_bfloat162 hi = __floats2bfloat162_rn(v.z, v.w);
    uint2 p = make_uint2(*reinterpret_cast<uint32_t*>(&lo),
                         *reinterpret_cast<uint32_t*>(&hi));
    *reinterpret_cast<uint2*>(dst + (size_t)blockIdx.y*CC*CC + i) = p;
}

// ---------------------------------------------------------------------------
// kv via MMA: per (bh, split): A = k^T[d][t], B = [v^T; ones][n][t]
// ---------------------------------------------------------------------------
__global__ void __launch_bounds__(256) kv_mma_kernel()
{
    __shared__ __nv_bfloat16 sA[2][64*72];
    __shared__ __nv_bfloat16 sB[2][72*72];
    const int blk = blockIdx.x;
    const int sp  = blk % KSPLIT;
    const int bh  = blk / KSPLIT;
    const int b = bh / HH, h = bh % HH;
    const int tid = threadIdx.x;
    const int wid = tid >> 5, lane = tid & 31;
    const int g = lane >> 2, t4 = lane & 3;
    const int wm = wid >> 2, wn = wid & 3;
    const int nt = (wn == 3) ? 3 : 2;

    const uint32_t suA[2] = {smem_u32(sA[0]), smem_u32(sA[1])};
    const uint32_t suB[2] = {smem_u32(sB[0]), smem_u32(sB[1])};

    for (int st = 0; st < 2; st++)
        for (int i = tid; i < 8*64; i += 256){
            int rr = i >> 6, cx = i & 63;
            sB[st][(64+rr)*72 + cx] = __float2bfloat16((rr == 0) ? 1.f : 0.f);
        }

    float acc[2][3][4];
    #pragma unroll
    for (int i = 0; i < 2; i++)
        #pragma unroll
        for (int j = 0; j < 3; j++)
            #pragma unroll
            for (int e = 0; e < 4; e++) acc[i][j][e] = 0.f;

    const __nv_bfloat16* Kb = g_kt + ((size_t)b*CC + h*DD)*TT + sp*(TT/KSPLIT);
    const __nv_bfloat16* Vb = g_vt + ((size_t)b*CC + h*DD)*TT + sp*(TT/KSPLIT);

    auto load_stage = [&](int st, int tc){
        #pragma unroll
        for (int r = 0; r < 2; r++){
            int i = tid + r*256;
            int row = i >> 3, cq = i & 7;
            CP_ASYNC16(suA[st] + (uint32_t)(row*72 + cq*8)*2,
                       Kb + (size_t)row*TT + tc*64 + cq*8);
            CP_ASYNC16(suB[st] + (uint32_t)(row*72 + cq*8)*2,
                       Vb + (size_t)row*TT + tc*64 + cq*8);
        }
    };

    const int NT = (TT/KSPLIT)/64;   // 8
    load_stage(0, 0); CP_COMMIT();

    for (int tc = 0; tc < NT; tc++){
        const int cur = tc & 1;
        if (tc + 1 < NT){ load_stage(cur^1, tc+1); CP_COMMIT(); CP_WAIT1(); }
        else            { CP_WAIT0(); }
        __syncthreads();

        const __nv_bfloat16* pa = sA[cur];
        const __nv_bfloat16* pb = sB[cur];
        #pragma unroll
        for (int s = 0; s < 4; s++){
            const int kb = s*16 + 2*t4;
            uint32_t ar[2][4], br[3][2];
            #pragma unroll
            for (int mf = 0; mf < 2; mf++){
                int r0 = wm*32 + mf*16 + g;
                ar[mf][0] = lds32(pa +  r0   *72 + kb);
                ar[mf][1] = lds32(pa + (r0+8)*72 + kb);
                ar[mf][2] = lds32(pa +  r0   *72 + kb + 8);
                ar[mf][3] = lds32(pa + (r0+8)*72 + kb + 8);
            }
            #pragma unroll
            for (int nf = 0; nf < 3; nf++){
                if (nf < nt){
                    int c0 = (nf == 2) ? (64 + g) : (wn*16 + nf*8 + g);
                    br[nf][0] = lds32(pb + c0*72 + kb);
                    br[nf][1] = lds32(pb + c0*72 + kb + 8);
                }
            }
            #pragma unroll
            for (int mf = 0; mf < 2; mf++)
                #pragma unroll
                for (int nf = 0; nf < 3; nf++)
                    if (nf < nt) mma_bf16(acc[mf][nf], ar[mf], br[nf]);
        }
        __syncthreads();
    }

    float* dst = g_kvP[sp][bh];
    #pragma unroll
    for (int mf = 0; mf < 2; mf++){
        const int m0 = wm*32 + mf*16 + g;
        #pragma unroll
        for (int nf = 0; nf < 3; nf++){
            if (nf >= nt) continue;
            const int n0 = (nf == 2) ? (64 + 2*t4) : (wn*16 + nf*8 + 2*t4);
            dst[(n0  )*64 + m0    ] = acc[mf][nf][0];
            dst[(n0+1)*64 + m0    ] = acc[mf][nf][1];
            dst[(n0  )*64 + m0 + 8] = acc[mf][nf][2];
            dst[(n0+1)*64 + m0 + 8] = acc[mf][nf][3];
        }
    }
}

// ---------------------------------------------------------------------------
// reduce KSPLIT kv partials -> bf16 slab g_kv16[bh][72*64]
// ---------------------------------------------------------------------------
__global__ void __launch_bounds__(256) kv_reduce_kernel()
{
    const int bh = blockIdx.x;
    const int tid = threadIdx.x;
    for (int i = tid; i < 72*64; i += 256){
        float s = 0.f;
        #pragma unroll
        for (int sp = 0; sp < KSPLIT; sp++) s += g_kvP[sp][bh][i];
        g_kv16[(size_t)bh*72*64 + i] = __float2bfloat16_rn(s);
    }
}

// ---------------------------------------------------------------------------
// attn via MMA: per (bh, 128-t chunk): A = q[t][d], B = [kv;ksum][n][d]
// ---------------------------------------------------------------------------
__global__ void __launch_bounds__(256) attn_mma_kernel()
{
    __shared__ __nv_bfloat16 sQ[128*72];
    __shared__ __nv_bfloat16 sB[72*72];
    const int blk = blockIdx.x;
    const int tc  = blk % (TT/128);
    const int bh  = blk / (TT/128);
    const int b = bh / HH, h = bh % HH;
    const int tid = threadIdx.x;
    const int wid = tid >> 5, lane = tid & 31;
    const int g = lane >> 2, t4 = lane & 3;
    const uint32_t suQ = smem_u32(sQ);

    // B: copy reduced bf16 kv slab (u32-vectorized)
    const uint32_t* src = reinterpret_cast<const uint32_t*>(g_kv16 + (size_t)bh*72*64);
    uint32_t* sBu = reinterpret_cast<uint32_t*>(sB);
    for (int i = tid; i < 72*32; i += 256){
        int n = i >> 5, d2 = i & 31;
        sBu[n*36 + d2] = src[i];
    }

    const __nv_bfloat16* Qb = g_q16 + (size_t)(b*TT + tc*128)*CC + h*DD;
    #pragma unroll
    for (int r = 0; r < 4; r++){
        int i = tid + r*256;
        int row = i >> 3, cq = i & 7;
        CP_ASYNC16(suQ + (uint32_t)(row*72 + cq*8)*2, Qb + (size_t)row*CC + cq*8);
    }
    CP_COMMIT(); CP_WAIT0();
    __syncthreads();

    float acc[9][4];
    #pragma unroll
    for (int i = 0; i < 9; i++)
        #pragma unroll
        for (int e = 0; e < 4; e++) acc[i][e] = 0.f;

    const int m0 = wid * 16;
    #pragma unroll
    for (int s = 0; s < 4; s++){
        const int kb = s*16 + 2*t4;
        uint32_t ar[4], br[9][2];
        ar[0] = lds32(sQ + (m0+g  )*72 + kb);
        ar[1] = lds32(sQ + (m0+g+8)*72 + kb);
        ar[2] = lds32(sQ + (m0+g  )*72 + kb + 8);
        ar[3] = lds32(sQ + (m0+g+8)*72 + kb + 8);
        #pragma unroll
        for (int nf = 0; nf < 9; nf++){
            int c0 = nf*8 + g;
            br[nf][0] = lds32(sB + c0*72 + kb);
            br[nf][1] = lds32(sB + c0*72 + kb + 8);
        }
        #pragma unroll
        for (int nf = 0; nf < 9; nf++)
            mma_bf16(acc[nf], ar, br[nf]);
    }

    float zlo = __shfl_sync(0xffffffffu, acc[8][0], lane & ~3);
    float zhi = __shfl_sync(0xffffffffu, acc[8][2], lane & ~3);
    const float rlo = 1.f / (zlo + 1e-6f);
    const float rhi = 1.f / (zhi + 1e-6f);

    const size_t row0 = (size_t)(b*TT + tc*128 + m0 + g);
    #pragma unroll
    for (int nf = 0; nf < 8; nf++){
        const int n0 = h*DD + nf*8 + 2*t4;
        *reinterpret_cast<__nv_bfloat162*>(g_attn16 +  row0     *CC + n0)
            = __floats2bfloat162_rn(acc[nf][0]*rlo, acc[nf][1]*rlo);
        *reinterpret_cast<__nv_bfloat162*>(g_attn16 + (row0 + 8)*CC + n0)
            = __floats2bfloat162_rn(acc[nf][2]*rhi, acc[nf][3]*rhi);
    }
}

// ---------------------------------------------------------------------------
extern "C" void kernel_launch(void* const* d_in, const int* in_sizes, int n_in,
                              void* d_out, int out_size)
{
    const float* x  = (const float*)d_in[0];
    const float* Wq = (const float*)d_in[1];
    const float* bq = (const float*)d_in[2];
    const float* Wk = (const float*)d_in[3];
    const float* bk = (const float*)d_in[4];
    const float* Wv = (const float*)d_in[5];
    const float* bv = (const float*)d_in[6];
    const float* Wo = (const float*)d_in[7];
    const float* bo = (const float*)d_in[8];
    float* out = (float*)d_out;

    __nv_bfloat16 *gxt, *gq, *gkt, *gvt, *gattn, *gw;
    cudaGetSymbolAddress((void**)&gxt,  g_xt);
    cudaGetSymbolAddress((void**)&gq,   g_q16);
    cudaGetSymbolAddress((void**)&gkt,  g_kt);
    cudaGetSymbolAddress((void**)&gvt,  g_vt);
    cudaGetSymbolAddress((void**)&gattn,g_attn16);
    cudaGetSymbolAddress((void**)&gw,   g_w16);

    cudaFuncSetAttribute(gemm_qkv, cudaFuncAttributeMaxDynamicSharedMemorySize, GEMM_SMEM);
    cudaFuncSetAttribute(gemm_out, cudaFuncAttributeMaxDynamicSharedMemorySize, GEMM_SMEM);

    // side stream + fork/join events (created once; not captured ops)
    static cudaStream_t s2 = nullptr;
    static cudaEvent_t eFork = nullptr, eW = nullptr, eKV = nullptr, eKVr = nullptr;
    if (s2 == nullptr){
        cudaStreamCreateWithFlags(&s2, cudaStreamNonBlocking);
        cudaEventCreateWithFlags(&eFork, cudaEventDisableTiming);
        cudaEventCreateWithFlags(&eW,    cudaEventDisableTiming);
        cudaEventCreateWithFlags(&eKV,   cudaEventDisableTiming);
        cudaEventCreateWithFlags(&eKVr,  cudaEventDisableTiming);
    }

    // fork: round_w on s2, transpose on main — independent
    cudaEventRecord(eFork, 0);
    cudaStreamWaitEvent(s2, eFork, 0);
    round_w4_kernel<<<dim3(CC*CC/1024, 4), 256, 0, s2>>>(Wq, Wk, Wv, Wo, gw);
    cudaEventRecord(eW, s2);

    transpose_round_kernel<<<dim3(TT/64, CC/64, BB), 256>>>(x);
    cudaStreamWaitEvent(0, eW, 0);       // weights ready before projections

    // K,V projections first (zoff=1 -> z=1,2)
    gemm_qkv<<<dim3(2, BT/128, CC/128), 256, GEMM_SMEM>>>(
        gxt, gw, bq, bk, bv, gq, gkt, gvt, 1);
    cudaEventRecord(eKV, 0);

    // kv einsum + reduce on s2, overlapping the Q projection on main
    cudaStreamWaitEvent(s2, eKV, 0);
    kv_mma_kernel<<<BB*HH*KSPLIT, 256, 0, s2>>>();
    kv_reduce_kernel<<<BB*HH, 256, 0, s2>>>();
    cudaEventRecord(eKVr, s2);

    // Q projection (zoff=0 -> z=0) on main, concurrent with kv
    gemm_qkv<<<dim3(1, BT/128, CC/128), 256, GEMM_SMEM>>>(
        gxt, gw, bq, bk, bv, gq, gkt, gvt, 0);

    // join: attn needs Q (main) + reduced kv (s2)
    cudaStreamWaitEvent(0, eKVr, 0);
    attn_mma_kernel<<<BB*HH*(TT/128), 256>>>();

    // output projection, n-fastest for A-tile L2 reuse
    gemm_out<<<dim3(CC/128, BT/128), 256, GEMM_SMEM>>>(
        gattn, gw + 3*(size_t)CC*CC, bo, x, out);
}

// round 12
// speedup vs baseline: 1.0006x; 1.0006x over previous
#include <cuda_runtime.h>
#include <cuda_bf16.h>
#include <math.h>
#include <stdint.h>

#define BB 4
#define CC 1024
#define TT 4096
#define HH 16
#define DD 64
#define BT (BB*TT)        // 16384
#define KSPLIT 8
#define NKCH 32           // K chunks of 32 per proj GEMM
#define SA 40             // GEMM smem row stride (bf16) — conflict-free for ldmatrix
#define NSTAGE 4

// ---------------- scratch (alloc-free: __device__ globals) ----------------
__device__ __nv_bfloat16 g_xt [(size_t)BT*CC];     // xt[bt][c]
__device__ __nv_bfloat16 g_q16[(size_t)BT*CC];     // q[bt][c]
__device__ __nv_bfloat16 g_kt [(size_t)BB*CC*TT];  // k^T[b*CC+c][t]
__device__ __nv_bfloat16 g_vt [(size_t)BB*CC*TT];  // v^T[b*CC+c][t]
__device__ __nv_bfloat16 g_attn16[(size_t)BT*CC];  // attn[bt][c]
__device__ __nv_bfloat16 g_w16[(size_t)4*CC*CC];   // Wq,Wk,Wv,Wo bf16
// kv partials: [split][bh][n(72: 0..63=kv cols e, 64=ksum)][d(64)]
__device__ float g_kvP[KSPLIT][BB*HH][72*64];
__device__ __nv_bfloat16 g_kv16[(size_t)BB*HH*72*64];   // reduced kv, bf16

// ---------------- helpers ----------------
__device__ __forceinline__ uint32_t smem_u32(const void* p){
    uint32_t a;
    asm("{ .reg .u64 t; cvta.to.shared.u64 t, %1; cvt.u32.u64 %0, t; }" : "=r"(a) : "l"(p));
    return a;
}

#define CP_ASYNC16(saddr, gptr) \
    asm volatile("cp.async.cg.shared.global [%0], [%1], 16;" :: "r"(saddr), "l"(gptr))
#define CP_COMMIT() asm volatile("cp.async.commit_group;" ::: "memory")
#define CP_WAIT2()  asm volatile("cp.async.wait_group 2;" ::: "memory")
#define CP_WAIT1()  asm volatile("cp.async.wait_group 1;" ::: "memory")
#define CP_WAIT0()  asm volatile("cp.async.wait_group 0;" ::: "memory")

// m16n8k16 bf16: D += A(16x16,row) * B(16x8, stored [n][k], k contiguous)
__device__ __forceinline__ void mma_bf16(float* c, const uint32_t* a, const uint32_t* b){
    asm volatile("mma.sync.aligned.m16n8k16.row.col.f32.bf16.bf16.f32 "
        "{%0,%1,%2,%3}, {%4,%5,%6,%7}, {%8,%9}, {%0,%1,%2,%3};"
        : "+f"(c[0]), "+f"(c[1]), "+f"(c[2]), "+f"(c[3])
        : "r"(a[0]), "r"(a[1]), "r"(a[2]), "r"(a[3]), "r"(b[0]), "r"(b[1]));
}
__device__ __forceinline__ uint32_t lds32(const __nv_bfloat16* p){
    return *reinterpret_cast<const uint32_t*>(p);
}
__device__ __forceinline__ void ldsm_x4(uint32_t* r, uint32_t addr){
    asm volatile("ldmatrix.sync.aligned.m8n8.x4.shared.b16 {%0,%1,%2,%3}, [%4];"
        : "=r"(r[0]), "=r"(r[1]), "=r"(r[2]), "=r"(r[3]) : "r"(addr));
}

#define STG (128*SA)                     // bf16 elements per operand per stage
#define GEMM_SMEM (NSTAGE*2*STG*2)       // bytes = 81920

// ---------------------------------------------------------------------------
// GEMM core: block 128x128, 8 warps (4m x 2n), warp tile 32x64,
// 4-stage cp.async (wait_group 2), ldmatrix.
// ---------------------------------------------------------------------------
struct GemmCtx {
    int tid, wid, lane, g, t4, wm, wn;
};

__device__ __forceinline__ void gemm_core(
    const __nv_bfloat16* __restrict__ Ab, const __nv_bfloat16* __restrict__ Bb,
    uint32_t su, const GemmCtx& c, float acc[2][8][4])
{
    const int rowA_l = (c.lane & 7) + 8*((c.lane >> 3) & 1);
    const int colA_l = 8*(c.lane >> 4);
    const int rowB_l = (c.lane & 7) + 8*(c.lane >> 4);
    const int colB_l = 8*((c.lane >> 3) & 1);

    auto load_stage = [&](int st, int kc){
        const uint32_t sa = su + (uint32_t)(st*2*STG)*2;
        const uint32_t sb = sa + (uint32_t)STG*2;
        const __nv_bfloat16* a = Ab + kc*32;
        const __nv_bfloat16* b = Bb + kc*32;
        #pragma unroll
        for (int r = 0; r < 2; r++){
            int i = c.tid + r*256;
            int row = i >> 2, cq = i & 3;
            CP_ASYNC16(sa + (uint32_t)(row*SA + cq*8)*2, a + (size_t)row*CC + cq*8);
            CP_ASYNC16(sb + (uint32_t)(row*SA + cq*8)*2, b + (size_t)row*CC + cq*8);
        }
        CP_COMMIT();
    };

    load_stage(0, 0);
    load_stage(1, 1);
    load_stage(2, 2);

    for (int kc = 0; kc < NKCH; kc++){
        if (kc < NKCH-2)       { CP_WAIT2(); }
        else if (kc == NKCH-2) { CP_WAIT1(); }
        else                   { CP_WAIT0(); }
        __syncthreads();
        if (kc + 3 < NKCH) load_stage((kc+3) % NSTAGE, kc+3);

        const int st = kc % NSTAGE;
        const uint32_t sa = su + (uint32_t)(st*2*STG)*2;
        const uint32_t sb = sa + (uint32_t)STG*2;
        #pragma unroll
        for (int s = 0; s < 2; s++){
            const int sk = s*16;
            uint32_t ar[2][4], br[4][4];
            #pragma unroll
            for (int mf = 0; mf < 2; mf++){
                int ml = c.wm*32 + mf*16;
                ldsm_x4(ar[mf], sa + (uint32_t)((ml + rowA_l)*SA + sk + colA_l)*2);
            }
            #pragma unroll
            for (int nf2 = 0; nf2 < 4; nf2++){
                int nl = c.wn*64 + nf2*16;
                ldsm_x4(br[nf2], sb + (uint32_t)((nl + rowB_l)*SA + sk + colB_l)*2);
            }
            #pragma unroll
            for (int mf = 0; mf < 2; mf++)
                #pragma unroll
                for (int nf = 0; nf < 8; nf++)
                    mma_bf16(acc[mf][nf], ar[mf], &br[nf >> 1][(nf & 1)*2]);
        }
    }
}

// ---------------------------------------------------------------------------
// Merged Q/K/V projection. Grid = (3, BT/128, CC/128): z FASTEST so the 24
// consecutive blocks (3 z x 8 n) sharing one A tile run in the same wave.
// ---------------------------------------------------------------------------
__global__ void __launch_bounds__(256, 2)
gemm_qkv(const __nv_bfloat16* __restrict__ A, const __nv_bfloat16* __restrict__ W,
         const float* __restrict__ bq, const float* __restrict__ bk,
         const float* __restrict__ bv,
         __nv_bfloat16* __restrict__ outq, __nv_bfloat16* __restrict__ outkt,
         __nv_bfloat16* __restrict__ outvt)
{
    extern __shared__ __nv_bfloat16 sm[];
    const uint32_t su = smem_u32(sm);
    GemmCtx c;
    c.tid = threadIdx.x; c.wid = c.tid >> 5; c.lane = c.tid & 31;
    c.g = c.lane >> 2; c.t4 = c.lane & 3;
    c.wm = c.wid >> 1;  c.wn = c.wid & 1;
    const int z  = blockIdx.x;
    const int bm = blockIdx.y * 128;
    const int bn = blockIdx.z * 128;

    const float* bias = (z == 0) ? bq : (z == 1) ? bk : bv;
    const __nv_bfloat16* Ab = A + (size_t)bm * CC;
    const __nv_bfloat16* Bb = W + (size_t)z*CC*CC + (size_t)bn * CC;

    float acc[2][8][4];
    #pragma unroll
    for (int i = 0; i < 2; i++)
        #pragma unroll
        for (int j = 0; j < 8; j++)
            #pragma unroll
            for (int e = 0; e < 4; e++) acc[i][j][e] = 0.f;

    gemm_core(Ab, Bb, su, c, acc);

    const bool act = (z != 2);
    #pragma unroll
    for (int mf = 0; mf < 2; mf++){
        const int m0 = bm + c.wm*32 + mf*16 + c.g;
        #pragma unroll
        for (int nf = 0; nf < 8; nf++){
            const int n0 = bn + c.wn*64 + nf*8 + c.t4*2;
            const float b0 = bias[n0], b1 = bias[n0+1];
            float v00 = acc[mf][nf][0] + b0;
            float v01 = acc[mf][nf][1] + b1;
            float v10 = acc[mf][nf][2] + b0;
            float v11 = acc[mf][nf][3] + b1;
            if (act){
                v00 = (v00 > 0.f) ? (v00 + 1.f) : expf(v00);
                v01 = (v01 > 0.f) ? (v01 + 1.f) : expf(v01);
                v10 = (v10 > 0.f) ? (v10 + 1.f) : expf(v10);
                v11 = (v11 > 0.f) ? (v11 + 1.f) : expf(v11);
            }
            if (z == 0){
                *reinterpret_cast<__nv_bfloat162*>(outq + (size_t) m0   *CC + n0)
                    = __floats2bfloat162_rn(v00, v01);
                *reinterpret_cast<__nv_bfloat162*>(outq + (size_t)(m0+8)*CC + n0)
                    = __floats2bfloat162_rn(v10, v11);
            } else {
                __nv_bfloat16* o = (z == 1) ? outkt : outvt;
                const int b = m0 / TT, t = m0 % TT;
                size_t r0i = ((size_t)b*CC + n0)*TT + t;
                size_t r1i = r0i + TT;
                o[r0i]     = __float2bfloat16_rn(v00);
                o[r1i]     = __float2bfloat16_rn(v01);
                o[r0i + 8] = __float2bfloat16_rn(v10);
                o[r1i + 8] = __float2bfloat16_rn(v11);
            }
        }
    }
}

// ---------------------------------------------------------------------------
// Output projection + bias + residual + transpose -> fp32 out[b][n][t]
// Grid = (CC/128, BT/128): n FASTEST so blocks sharing an A tile co-run.
// ---------------------------------------------------------------------------
__global__ void __launch_bounds__(256, 2)
gemm_out(const __nv_bfloat16* __restrict__ A, const __nv_bfloat16* __restrict__ W,
         const float* __restrict__ bias, const float* __restrict__ resid,
         float* __restrict__ outf)
{
    extern __shared__ __nv_bfloat16 sm[];
    const uint32_t su = smem_u32(sm);
    GemmCtx c;
    c.tid = threadIdx.x; c.wid = c.tid >> 5; c.lane = c.tid & 31;
    c.g = c.lane >> 2; c.t4 = c.lane & 3;
    c.wm = c.wid >> 1;  c.wn = c.wid & 1;
    const int bn = blockIdx.x * 128;
    const int bm = blockIdx.y * 128;

    const __nv_bfloat16* Ab = A + (size_t)bm * CC;
    const __nv_bfloat16* Bb = W + (size_t)bn * CC;

    float acc[2][8][4];
    #pragma unroll
    for (int i = 0; i < 2; i++)
        #pragma unroll
        for (int j = 0; j < 8; j++)
            #pragma unroll
            for (int e = 0; e < 4; e++) acc[i][j][e] = 0.f;

    gemm_core(Ab, Bb, su, c, acc);

    #pragma unroll
    for (int mf = 0; mf < 2; mf++){
        const int m0 = bm + c.wm*32 + mf*16 + c.g;
        const int b = m0 / TT, t = m0 % TT;
        #pragma unroll
        for (int nf = 0; nf < 8; nf++){
            const int n0 = bn + c.wn*64 + nf*8 + c.t4*2;
            size_t i00 = (size_t)b*CC*TT + (size_t)n0*TT + t;
            size_t i01 = i00 + TT;
            outf[i00]     = acc[mf][nf][0] + bias[n0]   + resid[i00];
            outf[i01]     = acc[mf][nf][1] + bias[n0+1] + resid[i01];
            outf[i00 + 8] = acc[mf][nf][2] + bias[n0]   + resid[i00 + 8];
            outf[i01 + 8] = acc[mf][nf][3] + bias[n0+1] + resid[i01 + 8];
        }
    }
}

// ---------------------------------------------------------------------------
// x[b,c,t] -> g_xt[b*T+t][c] bf16. 64x64 tiles, float4 loads, uint4 stores.
// ---------------------------------------------------------------------------
__global__ void __launch_bounds__(256) transpose_round_kernel(const float* __restrict__ x)
{
    __shared__ float tile[64][65];
    const int t0 = blockIdx.x * 64;
    const int c0 = blockIdx.y * 64;
    const int b  = blockIdx.z;
    const int tid = threadIdx.x;
    const int row = tid >> 2;            // c-row within tile
    const int q   = tid & 3;

    const float* src = x + (size_t)b*CC*TT + (size_t)(c0+row)*TT + t0 + q*16;
    #pragma unroll
    for (int j = 0; j < 4; j++){
        float4 v = *reinterpret_cast<const float4*>(src + j*4);
        tile[row][q*16 + j*4 + 0] = v.x;
        tile[row][q*16 + j*4 + 1] = v.y;
        tile[row][q*16 + j*4 + 2] = v.z;
        tile[row][q*16 + j*4 + 3] = v.w;
    }
    __syncthreads();

    uint32_t* dst = reinterpret_cast<uint32_t*>(
        g_xt + (size_t)(b*TT + t0 + row)*CC + c0);
    uint32_t tmp[8];
    #pragma unroll
    for (int j = 0; j < 8; j++){
        int cu = q*8 + j;                 // u32 column
        __nv_bfloat162 p = __floats2bfloat162_rn(tile[2*cu][row], tile[2*cu+1][row]);
        tmp[j] = *reinterpret_cast<uint32_t*>(&p);
    }
    *reinterpret_cast<uint4*>(dst + q*8)     = make_uint4(tmp[0], tmp[1], tmp[2], tmp[3]);
    *reinterpret_cast<uint4*>(dst + q*8 + 4) = make_uint4(tmp[4], tmp[5], tmp[6], tmp[7]);
}

// all 4 weights in one launch, vectorized x4: blockIdx.y selects the matrix
__global__ void round_w4_kernel(const float* __restrict__ w0, const float* __restrict__ w1,
                                const float* __restrict__ w2, const float* __restrict__ w3,
                                __nv_bfloat16* __restrict__ dst)
{
    const float* w = (blockIdx.y == 0) ? w0 : (blockIdx.y == 1) ? w1
                   : (blockIdx.y == 2) ? w2 : w3;
    int i = (blockIdx.x * 256 + threadIdx.x) * 4;
    float4 v = *reinterpret_cast<const float4*>(w + i);
    __nv_bfloat162 lo = __floats2bfloat162_rn(v.x, v.y);
    __nv_bfloat162 hi = __floats2bfloat162_rn(v.z, v.w);
    uint2 p = make_uint2(*reinterpret_cast<uint32_t*>(&lo),
                         *reinterpret_cast<uint32_t*>(&hi));
    *reinterpret_cast<uint2*>(dst + (size_t)blockIdx.y*CC*CC + i) = p;
}

// ---------------------------------------------------------------------------
// kv via MMA: per (bh, split): A = k^T[d][t], B = [v^T; ones][n][t]
// ---------------------------------------------------------------------------
__global__ void __launch_bounds__(256) kv_mma_kernel()
{
    __shared__ __nv_bfloat16 sA[2][64*72];
    __shared__ __nv_bfloat16 sB[2][72*72];
    const int blk = blockIdx.x;
    const int sp  = blk % KSPLIT;
    const int bh  = blk / KSPLIT;
    const int b = bh / HH, h = bh % HH;
    const int tid = threadIdx.x;
    const int wid = tid >> 5, lane = tid & 31;
    const int g = lane >> 2, t4 = lane & 3;
    const int wm = wid >> 2, wn = wid & 3;
    const int nt = (wn == 3) ? 3 : 2;

    const uint32_t suA[2] = {smem_u32(sA[0]), smem_u32(sA[1])};
    const uint32_t suB[2] = {smem_u32(sB[0]), smem_u32(sB[1])};

    for (int st = 0; st < 2; st++)
        for (int i = tid; i < 8*64; i += 256){
            int rr = i >> 6, cx = i & 63;
            sB[st][(64+rr)*72 + cx] = __float2bfloat16((rr == 0) ? 1.f : 0.f);
        }

    float acc[2][3][4];
    #pragma unroll
    for (int i = 0; i < 2; i++)
        #pragma unroll
        for (int j = 0; j < 3; j++)
            #pragma unroll
            for (int e = 0; e < 4; e++) acc[i][j][e] = 0.f;

    const __nv_bfloat16* Kb = g_kt + ((size_t)b*CC + h*DD)*TT + sp*(TT/KSPLIT);
    const __nv_bfloat16* Vb = g_vt + ((size_t)b*CC + h*DD)*TT + sp*(TT/KSPLIT);

    auto load_stage = [&](int st, int tc){
        #pragma unroll
        for (int r = 0; r < 2; r++){
            int i = tid + r*256;
            int row = i >> 3, cq = i & 7;
            CP_ASYNC16(suA[st] + (uint32_t)(row*72 + cq*8)*2,
                       Kb + (size_t)row*TT + tc*64 + cq*8);
            CP_ASYNC16(suB[st] + (uint32_t)(row*72 + cq*8)*2,
                       Vb + (size_t)row*TT + tc*64 + cq*8);
        }
    };

    const int NT = (TT/KSPLIT)/64;   // 8
    load_stage(0, 0); CP_COMMIT();

    for (int tc = 0; tc < NT; tc++){
        const int cur = tc & 1;
        if (tc + 1 < NT){ load_stage(cur^1, tc+1); CP_COMMIT(); CP_WAIT1(); }
        else            { CP_WAIT0(); }
        __syncthreads();

        const __nv_bfloat16* pa = sA[cur];
        const __nv_bfloat16* pb = sB[cur];
        #pragma unroll
        for (int s = 0; s < 4; s++){
            const int kb = s*16 + 2*t4;
            uint32_t ar[2][4], br[3][2];
            #pragma unroll
            for (int mf = 0; mf < 2; mf++){
                int r0 = wm*32 + mf*16 + g;
                ar[mf][0] = lds32(pa +  r0   *72 + kb);
                ar[mf][1] = lds32(pa + (r0+8)*72 + kb);
                ar[mf][2] = lds32(pa +  r0   *72 + kb + 8);
                ar[mf][3] = lds32(pa + (r0+8)*72 + kb + 8);
            }
            #pragma unroll
            for (int nf = 0; nf < 3; nf++){
                if (nf < nt){
                    int c0 = (nf == 2) ? (64 + g) : (wn*16 + nf*8 + g);
                    br[nf][0] = lds32(pb + c0*72 + kb);
                    br[nf][1] = lds32(pb + c0*72 + kb + 8);
                }
            }
            #pragma unroll
            for (int mf = 0; mf < 2; mf++)
                #pragma unroll
                for (int nf = 0; nf < 3; nf++)
                    if (nf < nt) mma_bf16(acc[mf][nf], ar[mf], br[nf]);
        }
        __syncthreads();
    }

    float* dst = g_kvP[sp][bh];
    #pragma unroll
    for (int mf = 0; mf < 2; mf++){
        const int m0 = wm*32 + mf*16 + g;
        #pragma unroll
        for (int nf = 0; nf < 3; nf++){
            if (nf >= nt) continue;
            const int n0 = (nf == 2) ? (64 + 2*t4) : (wn*16 + nf*8 + 2*t4);
            dst[(n0  )*64 + m0    ] = acc[mf][nf][0];
            dst[(n0+1)*64 + m0    ] = acc[mf][nf][1];
            dst[(n0  )*64 + m0 + 8] = acc[mf][nf][2];
            dst[(n0+1)*64 + m0 + 8] = acc[mf][nf][3];
        }
    }
}

// ---------------------------------------------------------------------------
// reduce KSPLIT kv partials -> bf16 slab g_kv16[bh][72*64]
// ---------------------------------------------------------------------------
__global__ void __launch_bounds__(256) kv_reduce_kernel()
{
    const int bh = blockIdx.x;
    const int tid = threadIdx.x;
    for (int i = tid; i < 72*64; i += 256){
        float s = 0.f;
        #pragma unroll
        for (int sp = 0; sp < KSPLIT; sp++) s += g_kvP[sp][bh][i];
        g_kv16[(size_t)bh*72*64 + i] = __float2bfloat16_rn(s);
    }
}

// ---------------------------------------------------------------------------
// attn via MMA: per (bh, 128-t chunk): A = q[t][d], B = [kv;ksum][n][d]
// ---------------------------------------------------------------------------
__global__ void __launch_bounds__(256) attn_mma_kernel()
{
    __shared__ __nv_bfloat16 sQ[128*72];
    __shared__ __nv_bfloat16 sB[72*72];
    const int blk = blockIdx.x;
    const int tc  = blk % (TT/128);
    const int bh  = blk / (TT/128);
    const int b = bh / HH, h = bh % HH;
    const int tid = threadIdx.x;
    const int wid = tid >> 5, lane = tid & 31;
    const int g = lane >> 2, t4 = lane & 3;
    const uint32_t suQ = smem_u32(sQ);

    // B: copy reduced bf16 kv slab (u32-vectorized)
    const uint32_t* src = reinterpret_cast<const uint32_t*>(g_kv16 + (size_t)bh*72*64);
    uint32_t* sBu = reinterpret_cast<uint32_t*>(sB);
    for (int i = tid; i < 72*32; i += 256){
        int n = i >> 5, d2 = i & 31;
        sBu[n*36 + d2] = src[i];
    }

    const __nv_bfloat16* Qb = g_q16 + (size_t)(b*TT + tc*128)*CC + h*DD;
    #pragma unroll
    for (int r = 0; r < 4; r++){
        int i = tid + r*256;
        int row = i >> 3, cq = i & 7;
        CP_ASYNC16(suQ + (uint32_t)(row*72 + cq*8)*2, Qb + (size_t)row*CC + cq*8);
    }
    CP_COMMIT(); CP_WAIT0();
    __syncthreads();

    float acc[9][4];
    #pragma unroll
    for (int i = 0; i < 9; i++)
        #pragma unroll
        for (int e = 0; e < 4; e++) acc[i][e] = 0.f;

    const int m0 = wid * 16;
    #pragma unroll
    for (int s = 0; s < 4; s++){
        const int kb = s*16 + 2*t4;
        uint32_t ar[4], br[9][2];
        ar[0] = lds32(sQ + (m0+g  )*72 + kb);
        ar[1] = lds32(sQ + (m0+g+8)*72 + kb);
        ar[2] = lds32(sQ + (m0+g  )*72 + kb + 8);
        ar[3] = lds32(sQ + (m0+g+8)*72 + kb + 8);
        #pragma unroll
        for (int nf = 0; nf < 9; nf++){
            int c0 = nf*8 + g;
            br[nf][0] = lds32(sB + c0*72 + kb);
            br[nf][1] = lds32(sB + c0*72 + kb + 8);
        }
        #pragma unroll
        for (int nf = 0; nf < 9; nf++)
            mma_bf16(acc[nf], ar, br[nf]);
    }

    float zlo = __shfl_sync(0xffffffffu, acc[8][0], lane & ~3);
    float zhi = __shfl_sync(0xffffffffu, acc[8][2], lane & ~3);
    const float rlo = 1.f / (zlo + 1e-6f);
    const float rhi = 1.f / (zhi + 1e-6f);

    const size_t row0 = (size_t)(b*TT + tc*128 + m0 + g);
    #pragma unroll
    for (int nf = 0; nf < 8; nf++){
        const int n0 = h*DD + nf*8 + 2*t4;
        *reinterpret_cast<__nv_bfloat162*>(g_attn16 +  row0     *CC + n0)
            = __floats2bfloat162_rn(acc[nf][0]*rlo, acc[nf][1]*rlo);
        *reinterpret_cast<__nv_bfloat162*>(g_attn16 + (row0 + 8)*CC + n0)
            = __floats2bfloat162_rn(acc[nf][2]*rhi, acc[nf][3]*rhi);
    }
}

// ---------------------------------------------------------------------------
extern "C" void kernel_launch(void* const* d_in, const int* in_sizes, int n_in,
                              void* d_out, int out_size)
{
    const float* x  = (const float*)d_in[0];
    const float* Wq = (const float*)d_in[1];
    const float* bq = (const float*)d_in[2];
    const float* Wk = (const float*)d_in[3];
    const float* bk = (const float*)d_in[4];
    const float* Wv = (const float*)d_in[5];
    const float* bv = (const float*)d_in[6];
    const float* Wo = (const float*)d_in[7];
    const float* bo = (const float*)d_in[8];
    float* out = (float*)d_out;

    __nv_bfloat16 *gxt, *gq, *gkt, *gvt, *gattn, *gw;
    cudaGetSymbolAddress((void**)&gxt,  g_xt);
    cudaGetSymbolAddress((void**)&gq,   g_q16);
    cudaGetSymbolAddress((void**)&gkt,  g_kt);
    cudaGetSymbolAddress((void**)&gvt,  g_vt);
    cudaGetSymbolAddress((void**)&gattn,g_attn16);
    cudaGetSymbolAddress((void**)&gw,   g_w16);

    cudaFuncSetAttribute(gemm_qkv, cudaFuncAttributeMaxDynamicSharedMemorySize, GEMM_SMEM);
    cudaFuncSetAttribute(gemm_out, cudaFuncAttributeMaxDynamicSharedMemorySize, GEMM_SMEM);

    // 1. pack inputs to bf16
    transpose_round_kernel<<<dim3(TT/64, CC/64, BB), 256>>>(x);
    round_w4_kernel<<<dim3(CC*CC/1024, 4), 256>>>(Wq, Wk, Wv, Wo, gw);

    // 2. Q/K/V projections merged, z-fastest for A-tile L2 reuse
    gemm_qkv<<<dim3(3, BT/128, CC/128), 256, GEMM_SMEM>>>(
        gxt, gw, bq, bk, bv, gq, gkt, gvt);

    // 3. linear attention (tensor cores)
    kv_mma_kernel<<<BB*HH*KSPLIT, 256>>>();
    kv_reduce_kernel<<<BB*HH, 256>>>();
    attn_mma_kernel<<<BB*HH*(TT/128), 256>>>();

    // 4. output projection, n-fastest for A-tile L2 reuse
    gemm_out<<<dim3(CC/128, BT/128), 256, GEMM_SMEM>>>(
        gattn, gw + 3*(size_t)CC*CC, bo, x, out);
}

// round 13
// speedup vs baseline: 1.0159x; 1.0153x over previous
#include <cuda_runtime.h>
#include <cuda_bf16.h>
#include <math.h>
#include <stdint.h>

#define BB 4
#define CC 1024
#define TT 4096
#define HH 16
#define DD 64
#define BT (BB*TT)        // 16384
#define KSPLIT 8
#define NKCH 32           // K chunks of 32 per proj GEMM
#define SA 40             // GEMM smem row stride (bf16) — conflict-free for ldmatrix

// ---------------- scratch (alloc-free: __device__ globals) ----------------
__device__ __nv_bfloat16 g_xt [(size_t)BT*CC];     // xt[bt][c]
__device__ __nv_bfloat16 g_q16[(size_t)BT*CC];     // q[bt][c]
__device__ __nv_bfloat16 g_kt [(size_t)BB*CC*TT];  // k^T[b*CC+c][t]
__device__ __nv_bfloat16 g_vt [(size_t)BB*CC*TT];  // v^T[b*CC+c][t]
__device__ __nv_bfloat16 g_attn16[(size_t)BT*CC];  // attn[bt][c]
__device__ __nv_bfloat16 g_w16[(size_t)4*CC*CC];   // Wq,Wk,Wv,Wo bf16
// kv partials: [split][bh][n(72: 0..63=kv cols e, 64=ksum)][d(64)]
__device__ float g_kvP[KSPLIT][BB*HH][72*64];
__device__ __nv_bfloat16 g_kv16[(size_t)BB*HH*72*64];   // reduced kv, bf16

// ---------------- helpers ----------------
__device__ __forceinline__ uint32_t smem_u32(const void* p){
    uint32_t a;
    asm("{ .reg .u64 t; cvta.to.shared.u64 t, %1; cvt.u32.u64 %0, t; }" : "=r"(a) : "l"(p));
    return a;
}

#define CP_ASYNC16(saddr, gptr) \
    asm volatile("cp.async.cg.shared.global [%0], [%1], 16;" :: "r"(saddr), "l"(gptr))
#define CP_COMMIT() asm volatile("cp.async.commit_group;" ::: "memory")
#define CP_WAIT1()  asm volatile("cp.async.wait_group 1;" ::: "memory")
#define CP_WAIT0()  asm volatile("cp.async.wait_group 0;" ::: "memory")

// m16n8k16 bf16: D += A(16x16,row) * B(16x8, stored [n][k], k contiguous)
__device__ __forceinline__ void mma_bf16(float* c, const uint32_t* a, const uint32_t* b){
    asm volatile("mma.sync.aligned.m16n8k16.row.col.f32.bf16.bf16.f32 "
        "{%0,%1,%2,%3}, {%4,%5,%6,%7}, {%8,%9}, {%0,%1,%2,%3};"
        : "+f"(c[0]), "+f"(c[1]), "+f"(c[2]), "+f"(c[3])
        : "r"(a[0]), "r"(a[1]), "r"(a[2]), "r"(a[3]), "r"(b[0]), "r"(b[1]));
}
__device__ __forceinline__ uint32_t lds32(const __nv_bfloat16* p){
    return *reinterpret_cast<const uint32_t*>(p);
}
__device__ __forceinline__ void ldsm_x4(uint32_t* r, uint32_t addr){
    asm volatile("ldmatrix.sync.aligned.m8n8.x4.shared.b16 {%0,%1,%2,%3}, [%4];"
        : "=r"(r[0]), "=r"(r[1]), "=r"(r[2]), "=r"(r[3]) : "r"(addr));
}

#define STG (128*SA)                 // bf16 elements per operand per stage
#define GEMM_SMEM (3*2*STG*2)        // bytes = 61440
#define TST 136                       // staging tile row stride (bf16), 272B rows

// ---------------------------------------------------------------------------
// GEMM core (proven R10): block 128x128, 8 warps (4m x 2n), warp tile 32x64,
// 3-stage cp.async, ldmatrix.
// ---------------------------------------------------------------------------
struct GemmCtx {
    int tid, wid, lane, g, t4, wm, wn;
};

__device__ __forceinline__ void gemm_core(
    const __nv_bfloat16* __restrict__ Ab, const __nv_bfloat16* __restrict__ Bb,
    uint32_t su, const GemmCtx& c, float acc[2][8][4])
{
    const int rowA_l = (c.lane & 7) + 8*((c.lane >> 3) & 1);
    const int colA_l = 8*(c.lane >> 4);
    const int rowB_l = (c.lane & 7) + 8*(c.lane >> 4);
    const int colB_l = 8*((c.lane >> 3) & 1);

    auto load_stage = [&](int st, int kc){
        const uint32_t sa = su + (uint32_t)(st*2*STG)*2;
        const uint32_t sb = sa + (uint32_t)STG*2;
        const __nv_bfloat16* a = Ab + kc*32;
        const __nv_bfloat16* b = Bb + kc*32;
        #pragma unroll
        for (int r = 0; r < 2; r++){
            int i = c.tid + r*256;
            int row = i >> 2, cq = i & 3;
            CP_ASYNC16(sa + (uint32_t)(row*SA + cq*8)*2, a + (size_t)row*CC + cq*8);
            CP_ASYNC16(sb + (uint32_t)(row*SA + cq*8)*2, b + (size_t)row*CC + cq*8);
        }
        CP_COMMIT();
    };

    load_stage(0, 0);
    load_stage(1, 1);

    for (int kc = 0; kc < NKCH; kc++){
        if (kc + 1 < NKCH) { CP_WAIT1(); } else { CP_WAIT0(); }
        __syncthreads();
        if (kc + 2 < NKCH) load_stage((kc+2) % 3, kc+2);

        const int st = kc % 3;
        const uint32_t sa = su + (uint32_t)(st*2*STG)*2;
        const uint32_t sb = sa + (uint32_t)STG*2;
        #pragma unroll
        for (int s = 0; s < 2; s++){
            const int sk = s*16;
            uint32_t ar[2][4], br[4][4];
            #pragma unroll
            for (int mf = 0; mf < 2; mf++){
                int ml = c.wm*32 + mf*16;
                ldsm_x4(ar[mf], sa + (uint32_t)((ml + rowA_l)*SA + sk + colA_l)*2);
            }
            #pragma unroll
            for (int nf2 = 0; nf2 < 4; nf2++){
                int nl = c.wn*64 + nf2*16;
                ldsm_x4(br[nf2], sb + (uint32_t)((nl + rowB_l)*SA + sk + colB_l)*2);
            }
            #pragma unroll
            for (int mf = 0; mf < 2; mf++)
                #pragma unroll
                for (int nf = 0; nf < 8; nf++)
                    mma_bf16(acc[mf][nf], ar[mf], &br[nf >> 1][(nf & 1)*2]);
        }
    }
}

// ---------------------------------------------------------------------------
// Merged Q/K/V projection. Grid = (3, BT/128, CC/128): z FASTEST so the 24
// consecutive blocks (3 z x 8 n) sharing one A tile run in the same wave.
// z==0 (Q): direct row-major bf16x2 stores.
// z==1/2 (K/V): stage 128x128 tile in SMEM [n][t], then uint4 coalesced store.
// ---------------------------------------------------------------------------
__global__ void __launch_bounds__(256, 2)
gemm_qkv(const __nv_bfloat16* __restrict__ A, const __nv_bfloat16* __restrict__ W,
         const float* __restrict__ bq, const float* __restrict__ bk,
         const float* __restrict__ bv,
         __nv_bfloat16* __restrict__ outq, __nv_bfloat16* __restrict__ outkt,
         __nv_bfloat16* __restrict__ outvt)
{
    extern __shared__ __nv_bfloat16 sm[];
    const uint32_t su = smem_u32(sm);
    GemmCtx c;
    c.tid = threadIdx.x; c.wid = c.tid >> 5; c.lane = c.tid & 31;
    c.g = c.lane >> 2; c.t4 = c.lane & 3;
    c.wm = c.wid >> 1;  c.wn = c.wid & 1;
    const int z  = blockIdx.x;
    const int bm = blockIdx.y * 128;
    const int bn = blockIdx.z * 128;

    const float* bias = (z == 0) ? bq : (z == 1) ? bk : bv;
    const __nv_bfloat16* Ab = A + (size_t)bm * CC;
    const __nv_bfloat16* Bb = W + (size_t)z*CC*CC + (size_t)bn * CC;

    float acc[2][8][4];
    #pragma unroll
    for (int i = 0; i < 2; i++)
        #pragma unroll
        for (int j = 0; j < 8; j++)
            #pragma unroll
            for (int e = 0; e < 4; e++) acc[i][j][e] = 0.f;

    gemm_core(Ab, Bb, su, c, acc);

    const bool act = (z != 2);
    if (z == 0){
        #pragma unroll
        for (int mf = 0; mf < 2; mf++){
            const int m0 = bm + c.wm*32 + mf*16 + c.g;
            #pragma unroll
            for (int nf = 0; nf < 8; nf++){
                const int n0 = bn + c.wn*64 + nf*8 + c.t4*2;
                const float b0 = bias[n0], b1 = bias[n0+1];
                float v00 = acc[mf][nf][0] + b0;
                float v01 = acc[mf][nf][1] + b1;
                float v10 = acc[mf][nf][2] + b0;
                float v11 = acc[mf][nf][3] + b1;
                v00 = (v00 > 0.f) ? (v00 + 1.f) : expf(v00);
                v01 = (v01 > 0.f) ? (v01 + 1.f) : expf(v01);
                v10 = (v10 > 0.f) ? (v10 + 1.f) : expf(v10);
                v11 = (v11 > 0.f) ? (v11 + 1.f) : expf(v11);
                *reinterpret_cast<__nv_bfloat162*>(outq + (size_t) m0   *CC + n0)
                    = __floats2bfloat162_rn(v00, v01);
                *reinterpret_cast<__nv_bfloat162*>(outq + (size_t)(m0+8)*CC + n0)
                    = __floats2bfloat162_rn(v10, v11);
            }
        }
    } else {
        __syncthreads();          // mainloop smem reads done on all warps
        #pragma unroll
        for (int mf = 0; mf < 2; mf++){
            const int tl = c.wm*32 + mf*16 + c.g;      // t within tile
            #pragma unroll
            for (int nf = 0; nf < 8; nf++){
                const int nl = c.wn*64 + nf*8 + c.t4*2; // n within tile
                const int n0 = bn + nl;
                const float b0 = bias[n0], b1 = bias[n0+1];
                float v00 = acc[mf][nf][0] + b0;
                float v01 = acc[mf][nf][1] + b1;
                float v10 = acc[mf][nf][2] + b0;
                float v11 = acc[mf][nf][3] + b1;
                if (act){
                    v00 = (v00 > 0.f) ? (v00 + 1.f) : expf(v00);
                    v01 = (v01 > 0.f) ? (v01 + 1.f) : expf(v01);
                    v10 = (v10 > 0.f) ? (v10 + 1.f) : expf(v10);
                    v11 = (v11 > 0.f) ? (v11 + 1.f) : expf(v11);
                }
                sm[ nl   *TST + tl    ] = __float2bfloat16_rn(v00);
                sm[(nl+1)*TST + tl    ] = __float2bfloat16_rn(v01);
                sm[ nl   *TST + tl + 8] = __float2bfloat16_rn(v10);
                sm[(nl+1)*TST + tl + 8] = __float2bfloat16_rn(v11);
            }
        }
        __syncthreads();
        __nv_bfloat16* o = (z == 1) ? outkt : outvt;
        const int b  = bm / TT;
        const int t0 = bm % TT;
        #pragma unroll
        for (int r = 0; r < 8; r++){
            int i = c.tid + r*256;               // 2048 uint4 transfers
            int row = i >> 4, cq = i & 15;
            *reinterpret_cast<uint4*>(o + ((size_t)b*CC + bn + row)*TT + t0 + cq*8)
                = *reinterpret_cast<const uint4*>(sm + row*TST + cq*8);
        }
    }
}

// ---------------------------------------------------------------------------
// Output projection + bias + residual + transpose -> fp32 out[b][n][t]
// Grid = (CC/128, BT/128): n FASTEST so blocks sharing an A tile co-run.
// ---------------------------------------------------------------------------
__global__ void __launch_bounds__(256, 2)
gemm_out(const __nv_bfloat16* __restrict__ A, const __nv_bfloat16* __restrict__ W,
         const float* __restrict__ bias, const float* __restrict__ resid,
         float* __restrict__ outf)
{
    extern __shared__ __nv_bfloat16 sm[];
    const uint32_t su = smem_u32(sm);
    GemmCtx c;
    c.tid = threadIdx.x; c.wid = c.tid >> 5; c.lane = c.tid & 31;
    c.g = c.lane >> 2; c.t4 = c.lane & 3;
    c.wm = c.wid >> 1;  c.wn = c.wid & 1;
    const int bn = blockIdx.x * 128;
    const int bm = blockIdx.y * 128;

    const __nv_bfloat16* Ab = A + (size_t)bm * CC;
    const __nv_bfloat16* Bb = W + (size_t)bn * CC;

    float acc[2][8][4];
    #pragma unroll
    for (int i = 0; i < 2; i++)
        #pragma unroll
        for (int j = 0; j < 8; j++)
            #pragma unroll
            for (int e = 0; e < 4; e++) acc[i][j][e] = 0.f;

    gemm_core(Ab, Bb, su, c, acc);

    #pragma unroll
    for (int mf = 0; mf < 2; mf++){
        const int m0 = bm + c.wm*32 + mf*16 + c.g;
        const int b = m0 / TT, t = m0 % TT;
        #pragma unroll
        for (int nf = 0; nf < 8; nf++){
            const int n0 = bn + c.wn*64 + nf*8 + c.t4*2;
            size_t i00 = (size_t)b*CC*TT + (size_t)n0*TT + t;
            size_t i01 = i00 + TT;
            outf[i00]     = acc[mf][nf][0] + bias[n0]   + resid[i00];
            outf[i01]     = acc[mf][nf][1] + bias[n0+1] + resid[i01];
            outf[i00 + 8] = acc[mf][nf][2] + bias[n0]   + resid[i00 + 8];
            outf[i01 + 8] = acc[mf][nf][3] + bias[n0+1] + resid[i01 + 8];
        }
    }
}

// ---------------------------------------------------------------------------
// x[b,c,t] -> g_xt[b*T+t][c] bf16. 64x64 tiles, float4 loads, uint4 stores.
// ---------------------------------------------------------------------------
__global__ void __launch_bounds__(256) transpose_round_kernel(const float* __restrict__ x)
{
    __shared__ float tile[64][65];
    const int t0 = blockIdx.x * 64;
    const int c0 = blockIdx.y * 64;
    const int b  = blockIdx.z;
    const int tid = threadIdx.x;
    const int row = tid >> 2;            // c-row within tile
    const int q   = tid & 3;

    const float* src = x + (size_t)b*CC*TT + (size_t)(c0+row)*TT + t0 + q*16;
    #pragma unroll
    for (int j = 0; j < 4; j++){
        float4 v = *reinterpret_cast<const float4*>(src + j*4);
        tile[row][q*16 + j*4 + 0] = v.x;
        tile[row][q*16 + j*4 + 1] = v.y;
        tile[row][q*16 + j*4 + 2] = v.z;
        tile[row][q*16 + j*4 + 3] = v.w;
    }
    __syncthreads();

    uint32_t* dst = reinterpret_cast<uint32_t*>(
        g_xt + (size_t)(b*TT + t0 + row)*CC + c0);
    uint32_t tmp[8];
    #pragma unroll
    for (int j = 0; j < 8; j++){
        int cu = q*8 + j;                 // u32 column
        __nv_bfloat162 p = __floats2bfloat162_rn(tile[2*cu][row], tile[2*cu+1][row]);
        tmp[j] = *reinterpret_cast<uint32_t*>(&p);
    }
    *reinterpret_cast<uint4*>(dst + q*8)     = make_uint4(tmp[0], tmp[1], tmp[2], tmp[3]);
    *reinterpret_cast<uint4*>(dst + q*8 + 4) = make_uint4(tmp[4], tmp[5], tmp[6], tmp[7]);
}

// all 4 weights in one launch, vectorized x4: blockIdx.y selects the matrix
__global__ void round_w4_kernel(const float* __restrict__ w0, const float* __restrict__ w1,
                                const float* __restrict__ w2, const float* __restrict__ w3,
                                __nv_bfloat16* __restrict__ dst)
{
    const float* w = (blockIdx.y == 0) ? w0 : (blockIdx.y == 1) ? w1
                   : (blockIdx.y == 2) ? w2 : w3;
    int i = (blockIdx.x * 256 + threadIdx.x) * 4;
    float4 v = *reinterpret_cast<const float4*>(w + i);
    __nv_bfloat162 lo = __floats2bfloat162_rn(v.x, v.y);
    __nv_bfloat162 hi = __floats2bfloat162_rn(v.z, v.w);
    uint2 p = make_uint2(*reinterpret_cast<uint32_t*>(&lo),
                         *reinterpret_cast<uint32_t*>(&hi));
    *reinterpret_cast<uint2*>(dst + (size_t)blockIdx.y*CC*CC + i) = p;
}

// ---------------------------------------------------------------------------
// kv via MMA: per (bh, split): A = k^T[d][t], B = [v^T; ones][n][t]
// ---------------------------------------------------------------------------
__global__ void __launch_bounds__(256) kv_mma_kernel()
{
    __shared__ __nv_bfloat16 sA[2][64*72];
    __shared__ __nv_bfloat16 sB[2][72*72];
    const int blk = blockIdx.x;
    const int sp  = blk % KSPLIT;
    const int bh  = blk / KSPLIT;
    const int b = bh / HH, h = bh % HH;
    const int tid = threadIdx.x;
    const int wid = tid >> 5, lane = tid & 31;
    const int g = lane >> 2, t4 = lane & 3;
    const int wm = wid >> 2, wn = wid & 3;
    const int nt = (wn == 3) ? 3 : 2;

    const uint32_t suA[2] = {smem_u32(sA[0]), smem_u32(sA[1])};
    const uint32_t suB[2] = {smem_u32(sB[0]), smem_u32(sB[1])};

    for (int st = 0; st < 2; st++)
        for (int i = tid; i < 8*64; i += 256){
            int rr = i >> 6, cx = i & 63;
            sB[st][(64+rr)*72 + cx] = __float2bfloat16((rr == 0) ? 1.f : 0.f);
        }

    float acc[2][3][4];
    #pragma unroll
    for (int i = 0; i < 2; i++)
        #pragma unroll
        for (int j = 0; j < 3; j++)
            #pragma unroll
            for (int e = 0; e < 4; e++) acc[i][j][e] = 0.f;

    const __nv_bfloat16* Kb = g_kt + ((size_t)b*CC + h*DD)*TT + sp*(TT/KSPLIT);
    const __nv_bfloat16* Vb = g_vt + ((size_t)b*CC + h*DD)*TT + sp*(TT/KSPLIT);

    auto load_stage = [&](int st, int tc){
        #pragma unroll
        for (int r = 0; r < 2; r++){
            int i = tid + r*256;
            int row = i >> 3, cq = i & 7;
            CP_ASYNC16(suA[st] + (uint32_t)(row*72 + cq*8)*2,
                       Kb + (size_t)row*TT + tc*64 + cq*8);
            CP_ASYNC16(suB[st] + (uint32_t)(row*72 + cq*8)*2,
                       Vb + (size_t)row*TT + tc*64 + cq*8);
        }
    };

    const int NT = (TT/KSPLIT)/64;   // 8
    load_stage(0, 0); CP_COMMIT();

    for (int tc = 0; tc < NT; tc++){
        const int cur = tc & 1;
        if (tc + 1 < NT){ load_stage(cur^1, tc+1); CP_COMMIT(); CP_WAIT1(); }
        else            { CP_WAIT0(); }
        __syncthreads();

        const __nv_bfloat16* pa = sA[cur];
        const __nv_bfloat16* pb = sB[cur];
        #pragma unroll
        for (int s = 0; s < 4; s++){
            const int kb = s*16 + 2*t4;
            uint32_t ar[2][4], br[3][2];
            #pragma unroll
            for (int mf = 0; mf < 2; mf++){
                int r0 = wm*32 + mf*16 + g;
                ar[mf][0] = lds32(pa +  r0   *72 + kb);
                ar[mf][1] = lds32(pa + (r0+8)*72 + kb);
                ar[mf][2] = lds32(pa +  r0   *72 + kb + 8);
                ar[mf][3] = lds32(pa + (r0+8)*72 + kb + 8);
            }
            #pragma unroll
            for (int nf = 0; nf < 3; nf++){
                if (nf < nt){
                    int c0 = (nf == 2) ? (64 + g) : (wn*16 + nf*8 + g);
                    br[nf][0] = lds32(pb + c0*72 + kb);
                    br[nf][1] = lds32(pb + c0*72 + kb + 8);
                }
            }
            #pragma unroll
            for (int mf = 0; mf < 2; mf++)
                #pragma unroll
                for (int nf = 0; nf < 3; nf++)
                    if (nf < nt) mma_bf16(acc[mf][nf], ar[mf], br[nf]);
        }
        __syncthreads();
    }

    float* dst = g_kvP[sp][bh];
    #pragma unroll
    for (int mf = 0; mf < 2; mf++){
        const int m0 = wm*32 + mf*16 + g;
        #pragma unroll
        for (int nf = 0; nf < 3; nf++){
            if (nf >= nt) continue;
            const int n0 = (nf == 2) ? (64 + 2*t4) : (wn*16 + nf*8 + 2*t4);
            dst[(n0  )*64 + m0    ] = acc[mf][nf][0];
            dst[(n0+1)*64 + m0    ] = acc[mf][nf][1];
            dst[(n0  )*64 + m0 + 8] = acc[mf][nf][2];
            dst[(n0+1)*64 + m0 + 8] = acc[mf][nf][3];
        }
    }
}

// ---------------------------------------------------------------------------
// reduce KSPLIT kv partials -> bf16 slab g_kv16[bh][72*64]
// ---------------------------------------------------------------------------
__global__ void __launch_bounds__(256) kv_reduce_kernel()
{
    const int bh = blockIdx.x;
    const int tid = threadIdx.x;
    for (int i = tid; i < 72*64; i += 256){
        float s = 0.f;
        #pragma unroll
        for (int sp = 0; sp < KSPLIT; sp++) s += g_kvP[sp][bh][i];
        g_kv16[(size_t)bh*72*64 + i] = __float2bfloat16_rn(s);
    }
}

// ---------------------------------------------------------------------------
// attn via MMA: per (bh, 128-t chunk): A = q[t][d], B = [kv;ksum][n][d]
// ---------------------------------------------------------------------------
__global__ void __launch_bounds__(256) attn_mma_kernel()
{
    __shared__ __nv_bfloat16 sQ[128*72];
    __shared__ __nv_bfloat16 sB[72*72];
    const int blk = blockIdx.x;
    const int tc  = blk % (TT/128);
    const int bh  = blk / (TT/128);
    const int b = bh / HH, h = bh % HH;
    const int tid = threadIdx.x;
    const int wid = tid >> 5, lane = tid & 31;
    const int g = lane >> 2, t4 = lane & 3;
    const uint32_t suQ = smem_u32(sQ);

    // B: copy reduced bf16 kv slab (u32-vectorized)
    const uint32_t* src = reinterpret_cast<const uint32_t*>(g_kv16 + (size_t)bh*72*64);
    uint32_t* sBu = reinterpret_cast<uint32_t*>(sB);
    for (int i = tid; i < 72*32; i += 256){
        int n = i >> 5, d2 = i & 31;
        sBu[n*36 + d2] = src[i];
    }

    const __nv_bfloat16* Qb = g_q16 + (size_t)(b*TT + tc*128)*CC + h*DD;
    #pragma unroll
    for (int r = 0; r < 4; r++){
        int i = tid + r*256;
        int row = i >> 3, cq = i & 7;
        CP_ASYNC16(suQ + (uint32_t)(row*72 + cq*8)*2, Qb + (size_t)row*CC + cq*8);
    }
    CP_COMMIT(); CP_WAIT0();
    __syncthreads();

    float acc[9][4];
    #pragma unroll
    for (int i = 0; i < 9; i++)
        #pragma unroll
        for (int e = 0; e < 4; e++) acc[i][e] = 0.f;

    const int m0 = wid * 16;
    #pragma unroll
    for (int s = 0; s < 4; s++){
        const int kb = s*16 + 2*t4;
        uint32_t ar[4], br[9][2];
        ar[0] = lds32(sQ + (m0+g  )*72 + kb);
        ar[1] = lds32(sQ + (m0+g+8)*72 + kb);
        ar[2] = lds32(sQ + (m0+g  )*72 + kb + 8);
        ar[3] = lds32(sQ + (m0+g+8)*72 + kb + 8);
        #pragma unroll
        for (int nf = 0; nf < 9; nf++){
            int c0 = nf*8 + g;
            br[nf][0] = lds32(sB + c0*72 + kb);
            br[nf][1] = lds32(sB + c0*72 + kb + 8);
        }
        #pragma unroll
        for (int nf = 0; nf < 9; nf++)
            mma_bf16(acc[nf], ar, br[nf]);
    }

    float zlo = __shfl_sync(0xffffffffu, acc[8][0], lane & ~3);
    float zhi = __shfl_sync(0xffffffffu, acc[8][2], lane & ~3);
    const float rlo = 1.f / (zlo + 1e-6f);
    const float rhi = 1.f / (zhi + 1e-6f);

    const size_t row0 = (size_t)(b*TT + tc*128 + m0 + g);
    #pragma unroll
    for (int nf = 0; nf < 8; nf++){
        const int n0 = h*DD + nf*8 + 2*t4;
        *reinterpret_cast<__nv_bfloat162*>(g_attn16 +  row0     *CC + n0)
            = __floats2bfloat162_rn(acc[nf][0]*rlo, acc[nf][1]*rlo);
        *reinterpret_cast<__nv_bfloat162*>(g_attn16 + (row0 + 8)*CC + n0)
            = __floats2bfloat162_rn(acc[nf][2]*rhi, acc[nf][3]*rhi);
    }
}

// ---------------------------------------------------------------------------
extern "C" void kernel_launch(void* const* d_in, const int* in_sizes, int n_in,
                              void* d_out, int out_size)
{
    const float* x  = (const float*)d_in[0];
    const float* Wq = (const float*)d_in[1];
    const float* bq = (const float*)d_in[2];
    const float* Wk = (const float*)d_in[3];
    const float* bk = (const float*)d_in[4];
    const float* Wv = (const float*)d_in[5];
    const float* bv = (const float*)d_in[6];
    const float* Wo = (const float*)d_in[7];
    const float* bo = (const float*)d_in[8];
    float* out = (float*)d_out;

    __nv_bfloat16 *gxt, *gq, *gkt, *gvt, *gattn, *gw;
    cudaGetSymbolAddress((void**)&gxt,  g_xt);
    cudaGetSymbolAddress((void**)&gq,   g_q16);
    cudaGetSymbolAddress((void**)&gkt,  g_kt);
    cudaGetSymbolAddress((void**)&gvt,  g_vt);
    cudaGetSymbolAddress((void**)&gattn,g_attn16);
    cudaGetSymbolAddress((void**)&gw,   g_w16);

    cudaFuncSetAttribute(gemm_qkv, cudaFuncAttributeMaxDynamicSharedMemorySize, GEMM_SMEM);
    cudaFuncSetAttribute(gemm_out, cudaFuncAttributeMaxDynamicSharedMemorySize, GEMM_SMEM);

    // 1. pack inputs to bf16
    transpose_round_kernel<<<dim3(TT/64, CC/64, BB), 256>>>(x);
    round_w4_kernel<<<dim3(CC*CC/1024, 4), 256>>>(Wq, Wk, Wv, Wo, gw);

    // 2. Q/K/V projections merged, z-fastest for A-tile L2 reuse
    gemm_qkv<<<dim3(3, BT/128, CC/128), 256, GEMM_SMEM>>>(
        gxt, gw, bq, bk, bv, gq, gkt, gvt);

    // 3. linear attention (tensor cores)
    kv_mma_kernel<<<BB*HH*KSPLIT, 256>>>();
    kv_reduce_kernel<<<BB*HH, 256>>>();
    attn_mma_kernel<<<BB*HH*(TT/128), 256>>>();

    // 4. output projection, n-fastest for A-tile L2 reuse
    gemm_out<<<dim3(CC/128, BT/128), 256, GEMM_SMEM>>>(
        gattn, gw + 3*(size_t)CC*CC, bo, x, out);
}

// round 14
// speedup vs baseline: 1.0379x; 1.0216x over previous
#include <cuda_runtime.h>
#include <cuda_bf16.h>
#include <math.h>
#include <stdint.h>

#define BB 4
#define CC 1024
#define TT 4096
#define HH 16
#define DD 64
#define BT (BB*TT)        // 16384
#define KSPLIT 8
#define NKCH 16           // K chunks of 64 per proj GEMM
#define SA 72             // GEMM smem row stride (bf16) — conflict-free for ldmatrix

// ---------------- scratch (alloc-free: __device__ globals) ----------------
__device__ __nv_bfloat16 g_xt [(size_t)BT*CC];     // xt[bt][c]
__device__ __nv_bfloat16 g_q16[(size_t)BT*CC];     // q[bt][c]
__device__ __nv_bfloat16 g_kt [(size_t)BB*CC*TT];  // k^T[b*CC+c][t]
__device__ __nv_bfloat16 g_vt [(size_t)BB*CC*TT];  // v^T[b*CC+c][t]
__device__ __nv_bfloat16 g_attn16[(size_t)BT*CC];  // attn[bt][c]
__device__ __nv_bfloat16 g_w16[(size_t)4*CC*CC];   // Wq,Wk,Wv,Wo bf16
// kv partials: [split][bh][n(72: 0..63=kv cols e, 64=ksum)][d(64)]
__device__ float g_kvP[KSPLIT][BB*HH][72*64];
__device__ __nv_bfloat16 g_kv16[(size_t)BB*HH*72*64];   // reduced kv, bf16

// ---------------- helpers ----------------
__device__ __forceinline__ uint32_t smem_u32(const void* p){
    uint32_t a;
    asm("{ .reg .u64 t; cvta.to.shared.u64 t, %1; cvt.u32.u64 %0, t; }" : "=r"(a) : "l"(p));
    return a;
}

#define CP_ASYNC16(saddr, gptr) \
    asm volatile("cp.async.cg.shared.global [%0], [%1], 16;" :: "r"(saddr), "l"(gptr))
#define CP_COMMIT() asm volatile("cp.async.commit_group;" ::: "memory")
#define CP_WAIT1()  asm volatile("cp.async.wait_group 1;" ::: "memory")
#define CP_WAIT0()  asm volatile("cp.async.wait_group 0;" ::: "memory")

// m16n8k16 bf16: D += A(16x16,row) * B(16x8, stored [n][k], k contiguous)
__device__ __forceinline__ void mma_bf16(float* c, const uint32_t* a, const uint32_t* b){
    asm volatile("mma.sync.aligned.m16n8k16.row.col.f32.bf16.bf16.f32 "
        "{%0,%1,%2,%3}, {%4,%5,%6,%7}, {%8,%9}, {%0,%1,%2,%3};"
        : "+f"(c[0]), "+f"(c[1]), "+f"(c[2]), "+f"(c[3])
        : "r"(a[0]), "r"(a[1]), "r"(a[2]), "r"(a[3]), "r"(b[0]), "r"(b[1]));
}
__device__ __forceinline__ uint32_t lds32(const __nv_bfloat16* p){
    return *reinterpret_cast<const uint32_t*>(p);
}
__device__ __forceinline__ void ldsm_x4(uint32_t* r, uint32_t addr){
    asm volatile("ldmatrix.sync.aligned.m8n8.x4.shared.b16 {%0,%1,%2,%3}, [%4];"
        : "=r"(r[0]), "=r"(r[1]), "=r"(r[2]), "=r"(r[3]) : "r"(addr));
}

#define STG (128*SA)                 // bf16 elements per operand per stage
#define GEMM_SMEM (3*2*STG*2)        // bytes = 110592  (2 blocks/SM: 221 KB <= 228)

// ---------------------------------------------------------------------------
// GEMM core: block 128x128, 8 warps (4m x 2n), warp tile 32x64,
// 3-stage cp.async, K-chunk 64 (4 k16 steps per chunk), ldmatrix.
// ---------------------------------------------------------------------------
struct GemmCtx {
    int tid, wid, lane, g, t4, wm, wn;
};

__device__ __forceinline__ void gemm_core(
    const __nv_bfloat16* __restrict__ Ab, const __nv_bfloat16* __restrict__ Bb,
    uint32_t su, const GemmCtx& c, float acc[2][8][4])
{
    const int rowA_l = (c.lane & 7) + 8*((c.lane >> 3) & 1);
    const int colA_l = 8*(c.lane >> 4);
    const int rowB_l = (c.lane & 7) + 8*(c.lane >> 4);
    const int colB_l = 8*((c.lane >> 3) & 1);

    auto load_stage = [&](int st, int kc){
        const uint32_t sa = su + (uint32_t)(st*2*STG)*2;
        const uint32_t sb = sa + (uint32_t)STG*2;
        const __nv_bfloat16* a = Ab + kc*64;
        const __nv_bfloat16* b = Bb + kc*64;
        #pragma unroll
        for (int r = 0; r < 4; r++){
            int i = c.tid + r*256;           // 1024 x 16B per operand
            int row = i >> 3, cq = i & 7;
            CP_ASYNC16(sa + (uint32_t)(row*SA + cq*8)*2, a + (size_t)row*CC + cq*8);
            CP_ASYNC16(sb + (uint32_t)(row*SA + cq*8)*2, b + (size_t)row*CC + cq*8);
        }
        CP_COMMIT();
    };

    load_stage(0, 0);
    load_stage(1, 1);

    for (int kc = 0; kc < NKCH; kc++){
        if (kc + 1 < NKCH) { CP_WAIT1(); } else { CP_WAIT0(); }
        __syncthreads();
        if (kc + 2 < NKCH) load_stage((kc+2) % 3, kc+2);

        const int st = kc % 3;
        const uint32_t sa = su + (uint32_t)(st*2*STG)*2;
        const uint32_t sb = sa + (uint32_t)STG*2;
        #pragma unroll
        for (int s = 0; s < 4; s++){
            const int sk = s*16;
            uint32_t ar[2][4], br[4][4];
            #pragma unroll
            for (int mf = 0; mf < 2; mf++){
                int ml = c.wm*32 + mf*16;
                ldsm_x4(ar[mf], sa + (uint32_t)((ml + rowA_l)*SA + sk + colA_l)*2);
            }
            #pragma unroll
            for (int nf2 = 0; nf2 < 4; nf2++){
                int nl = c.wn*64 + nf2*16;
                ldsm_x4(br[nf2], sb + (uint32_t)((nl + rowB_l)*SA + sk + colB_l)*2);
            }
            #pragma unroll
            for (int mf = 0; mf < 2; mf++)
                #pragma unroll
                for (int nf = 0; nf < 8; nf++)
                    mma_bf16(acc[mf][nf], ar[mf], &br[nf >> 1][(nf & 1)*2]);
        }
    }
}

// ---------------------------------------------------------------------------
// Merged Q/K/V projection. Grid = (3, BT/128, CC/128): z FASTEST so the 24
// consecutive blocks (3 z x 8 n) sharing one A tile run in the same wave.
// ---------------------------------------------------------------------------
__global__ void __launch_bounds__(256, 2)
gemm_qkv(const __nv_bfloat16* __restrict__ A, const __nv_bfloat16* __restrict__ W,
         const float* __restrict__ bq, const float* __restrict__ bk,
         const float* __restrict__ bv,
         __nv_bfloat16* __restrict__ outq, __nv_bfloat16* __restrict__ outkt,
         __nv_bfloat16* __restrict__ outvt)
{
    extern __shared__ __nv_bfloat16 sm[];
    const uint32_t su = smem_u32(sm);
    GemmCtx c;
    c.tid = threadIdx.x; c.wid = c.tid >> 5; c.lane = c.tid & 31;
    c.g = c.lane >> 2; c.t4 = c.lane & 3;
    c.wm = c.wid >> 1;  c.wn = c.wid & 1;
    const int z  = blockIdx.x;
    const int bm = blockIdx.y * 128;
    const int bn = blockIdx.z * 128;

    const float* bias = (z == 0) ? bq : (z == 1) ? bk : bv;
    const __nv_bfloat16* Ab = A + (size_t)bm * CC;
    const __nv_bfloat16* Bb = W + (size_t)z*CC*CC + (size_t)bn * CC;

    float acc[2][8][4];
    #pragma unroll
    for (int i = 0; i < 2; i++)
        #pragma unroll
        for (int j = 0; j < 8; j++)
            #pragma unroll
            for (int e = 0; e < 4; e++) acc[i][j][e] = 0.f;

    gemm_core(Ab, Bb, su, c, acc);

    const bool act = (z != 2);
    #pragma unroll
    for (int mf = 0; mf < 2; mf++){
        const int m0 = bm + c.wm*32 + mf*16 + c.g;
        #pragma unroll
        for (int nf = 0; nf < 8; nf++){
            const int n0 = bn + c.wn*64 + nf*8 + c.t4*2;
            const float b0 = bias[n0], b1 = bias[n0+1];
            float v00 = acc[mf][nf][0] + b0;
            float v01 = acc[mf][nf][1] + b1;
            float v10 = acc[mf][nf][2] + b0;
            float v11 = acc[mf][nf][3] + b1;
            if (act){
                v00 = (v00 > 0.f) ? (v00 + 1.f) : expf(v00);
                v01 = (v01 > 0.f) ? (v01 + 1.f) : expf(v01);
                v10 = (v10 > 0.f) ? (v10 + 1.f) : expf(v10);
                v11 = (v11 > 0.f) ? (v11 + 1.f) : expf(v11);
            }
            if (z == 0){
                *reinterpret_cast<__nv_bfloat162*>(outq + (size_t) m0   *CC + n0)
                    = __floats2bfloat162_rn(v00, v01);
                *reinterpret_cast<__nv_bfloat162*>(outq + (size_t)(m0+8)*CC + n0)
                    = __floats2bfloat162_rn(v10, v11);
            } else {
                __nv_bfloat16* o = (z == 1) ? outkt : outvt;
                const int b = m0 / TT, t = m0 % TT;
                size_t r0i = ((size_t)b*CC + n0)*TT + t;
                size_t r1i = r0i + TT;
                o[r0i]     = __float2bfloat16_rn(v00);
                o[r1i]     = __float2bfloat16_rn(v01);
                o[r0i + 8] = __float2bfloat16_rn(v10);
                o[r1i + 8] = __float2bfloat16_rn(v11);
            }
        }
    }
}

// ---------------------------------------------------------------------------
// Output projection + bias + residual + transpose -> fp32 out[b][n][t]
// Grid = (CC/128, BT/128): n FASTEST so blocks sharing an A tile co-run.
// ---------------------------------------------------------------------------
__global__ void __launch_bounds__(256, 2)
gemm_out(const __nv_bfloat16* __restrict__ A, const __nv_bfloat16* __restrict__ W,
         const float* __restrict__ bias, const float* __restrict__ resid,
         float* __restrict__ outf)
{
    extern __shared__ __nv_bfloat16 sm[];
    const uint32_t su = smem_u32(sm);
    GemmCtx c;
    c.tid = threadIdx.x; c.wid = c.tid >> 5; c.lane = c.tid & 31;
    c.g = c.lane >> 2; c.t4 = c.lane & 3;
    c.wm = c.wid >> 1;  c.wn = c.wid & 1;
    const int bn = blockIdx.x * 128;
    const int bm = blockIdx.y * 128;

    const __nv_bfloat16* Ab = A + (size_t)bm * CC;
    const __nv_bfloat16* Bb = W + (size_t)bn * CC;

    float acc[2][8][4];
    #pragma unroll
    for (int i = 0; i < 2; i++)
        #pragma unroll
        for (int j = 0; j < 8; j++)
            #pragma unroll
            for (int e = 0; e < 4; e++) acc[i][j][e] = 0.f;

    gemm_core(Ab, Bb, su, c, acc);

    #pragma unroll
    for (int mf = 0; mf < 2; mf++){
        const int m0 = bm + c.wm*32 + mf*16 + c.g;
        const int b = m0 / TT, t = m0 % TT;
        #pragma unroll
        for (int nf = 0; nf < 8; nf++){
            const int n0 = bn + c.wn*64 + nf*8 + c.t4*2;
            size_t i00 = (size_t)b*CC*TT + (size_t)n0*TT + t;
            size_t i01 = i00 + TT;
            outf[i00]     = acc[mf][nf][0] + bias[n0]   + resid[i00];
            outf[i01]     = acc[mf][nf][1] + bias[n0+1] + resid[i01];
            outf[i00 + 8] = acc[mf][nf][2] + bias[n0]   + resid[i00 + 8];
            outf[i01 + 8] = acc[mf][nf][3] + bias[n0+1] + resid[i01 + 8];
        }
    }
}

// ---------------------------------------------------------------------------
// x[b,c,t] -> g_xt[b*T+t][c] bf16. 64x64 tiles, float4 loads, uint4 stores.
// ---------------------------------------------------------------------------
__global__ void __launch_bounds__(256) transpose_round_kernel(const float* __restrict__ x)
{
    __shared__ float tile[64][65];
    const int t0 = blockIdx.x * 64;
    const int c0 = blockIdx.y * 64;
    const int b  = blockIdx.z;
    const int tid = threadIdx.x;
    const int row = tid >> 2;            // c-row within tile
    const int q   = tid & 3;

    const float* src = x + (size_t)b*CC*TT + (size_t)(c0+row)*TT + t0 + q*16;
    #pragma unroll
    for (int j = 0; j < 4; j++){
        float4 v = *reinterpret_cast<const float4*>(src + j*4);
        tile[row][q*16 + j*4 + 0] = v.x;
        tile[row][q*16 + j*4 + 1] = v.y;
        tile[row][q*16 + j*4 + 2] = v.z;
        tile[row][q*16 + j*4 + 3] = v.w;
    }
    __syncthreads();

    uint32_t* dst = reinterpret_cast<uint32_t*>(
        g_xt + (size_t)(b*TT + t0 + row)*CC + c0);
    uint32_t tmp[8];
    #pragma unroll
    for (int j = 0; j < 8; j++){
        int cu = q*8 + j;                 // u32 column
        __nv_bfloat162 p = __floats2bfloat162_rn(tile[2*cu][row], tile[2*cu+1][row]);
        tmp[j] = *reinterpret_cast<uint32_t*>(&p);
    }
    *reinterpret_cast<uint4*>(dst + q*8)     = make_uint4(tmp[0], tmp[1], tmp[2], tmp[3]);
    *reinterpret_cast<uint4*>(dst + q*8 + 4) = make_uint4(tmp[4], tmp[5], tmp[6], tmp[7]);
}

// all 4 weights in one launch, vectorized x4: blockIdx.y selects the matrix
__global__ void round_w4_kernel(const float* __restrict__ w0, const float* __restrict__ w1,
                                const float* __restrict__ w2, const float* __restrict__ w3,
                                __nv_bfloat16* __restrict__ dst)
{
    const float* w = (blockIdx.y == 0) ? w0 : (blockIdx.y == 1) ? w1
                   : (blockIdx.y == 2) ? w2 : w3;
    int i = (blockIdx.x * 256 + threadIdx.x) * 4;
    float4 v = *reinterpret_cast<const float4*>(w + i);
    __nv_bfloat162 lo = __floats2bfloat162_rn(v.x, v.y);
    __nv_bfloat162 hi = __floats2bfloat162_rn(v.z, v.w);
    uint2 p = make_uint2(*reinterpret_cast<uint32_t*>(&lo),
                         *reinterpret_cast<uint32_t*>(&hi));
    *reinterpret_cast<uint2*>(dst + (size_t)blockIdx.y*CC*CC + i) = p;
}

// ---------------------------------------------------------------------------
// kv via MMA: per (bh, split): A = k^T[d][t], B = [v^T; ones][n][t]
// ---------------------------------------------------------------------------
__global__ void __launch_bounds__(256) kv_mma_kernel()
{
    __shared__ __nv_bfloat16 sA[2][64*72];
    __shared__ __nv_bfloat16 sB[2][72*72];
    const int blk = blockIdx.x;
    const int sp  = blk % KSPLIT;
    const int bh  = blk / KSPLIT;
    const int b = bh / HH, h = bh % HH;
    const int tid = threadIdx.x;
    const int wid = tid >> 5, lane = tid & 31;
    const int g = lane >> 2, t4 = lane & 3;
    const int wm = wid >> 2, wn = wid & 3;
    const int nt = (wn == 3) ? 3 : 2;

    const uint32_t suA[2] = {smem_u32(sA[0]), smem_u32(sA[1])};
    const uint32_t suB[2] = {smem_u32(sB[0]), smem_u32(sB[1])};

    for (int st = 0; st < 2; st++)
        for (int i = tid; i < 8*64; i += 256){
            int rr = i >> 6, cx = i & 63;
            sB[st][(64+rr)*72 + cx] = __float2bfloat16((rr == 0) ? 1.f : 0.f);
        }

    float acc[2][3][4];
    #pragma unroll
    for (int i = 0; i < 2; i++)
        #pragma unroll
        for (int j = 0; j < 3; j++)
            #pragma unroll
            for (int e = 0; e < 4; e++) acc[i][j][e] = 0.f;

    const __nv_bfloat16* Kb = g_kt + ((size_t)b*CC + h*DD)*TT + sp*(TT/KSPLIT);
    const __nv_bfloat16* Vb = g_vt + ((size_t)b*CC + h*DD)*TT + sp*(TT/KSPLIT);

    auto load_stage = [&](int st, int tc){
        #pragma unroll
        for (int r = 0; r < 2; r++){
            int i = tid + r*256;
            int row = i >> 3, cq = i & 7;
            CP_ASYNC16(suA[st] + (uint32_t)(row*72 + cq*8)*2,
                       Kb + (size_t)row*TT + tc*64 + cq*8);
            CP_ASYNC16(suB[st] + (uint32_t)(row*72 + cq*8)*2,
                       Vb + (size_t)row*TT + tc*64 + cq*8);
        }
    };

    const int NT = (TT/KSPLIT)/64;   // 8
    load_stage(0, 0); CP_COMMIT();

    for (int tc = 0; tc < NT; tc++){
        const int cur = tc & 1;
        if (tc + 1 < NT){ load_stage(cur^1, tc+1); CP_COMMIT(); CP_WAIT1(); }
        else            { CP_WAIT0(); }
        __syncthreads();

        const __nv_bfloat16* pa = sA[cur];
        const __nv_bfloat16* pb = sB[cur];
        #pragma unroll
        for (int s = 0; s < 4; s++){
            const int kb = s*16 + 2*t4;
            uint32_t ar[2][4], br[3][2];
            #pragma unroll
            for (int mf = 0; mf < 2; mf++){
                int r0 = wm*32 + mf*16 + g;
                ar[mf][0] = lds32(pa +  r0   *72 + kb);
                ar[mf][1] = lds32(pa + (r0+8)*72 + kb);
                ar[mf][2] = lds32(pa +  r0   *72 + kb + 8);
                ar[mf][3] = lds32(pa + (r0+8)*72 + kb + 8);
            }
            #pragma unroll
            for (int nf = 0; nf < 3; nf++){
                if (nf < nt){
                    int c0 = (nf == 2) ? (64 + g) : (wn*16 + nf*8 + g);
                    br[nf][0] = lds32(pb + c0*72 + kb);
                    br[nf][1] = lds32(pb + c0*72 + kb + 8);
                }
            }
            #pragma unroll
            for (int mf = 0; mf < 2; mf++)
                #pragma unroll
                for (int nf = 0; nf < 3; nf++)
                    if (nf < nt) mma_bf16(acc[mf][nf], ar[mf], br[nf]);
        }
        __syncthreads();
    }

    float* dst = g_kvP[sp][bh];
    #pragma unroll
    for (int mf = 0; mf < 2; mf++){
        const int m0 = wm*32 + mf*16 + g;
        #pragma unroll
        for (int nf = 0; nf < 3; nf++){
            if (nf >= nt) continue;
            const int n0 = (nf == 2) ? (64 + 2*t4) : (wn*16 + nf*8 + 2*t4);
            dst[(n0  )*64 + m0    ] = acc[mf][nf][0];
            dst[(n0+1)*64 + m0    ] = acc[mf][nf][1];
            dst[(n0  )*64 + m0 + 8] = acc[mf][nf][2];
            dst[(n0+1)*64 + m0 + 8] = acc[mf][nf][3];
        }
    }
}

// ---------------------------------------------------------------------------
// reduce KSPLIT kv partials -> bf16 slab g_kv16[bh][72*64]
// ---------------------------------------------------------------------------
__global__ void __launch_bounds__(256) kv_reduce_kernel()
{
    const int bh = blockIdx.x;
    const int tid = threadIdx.x;
    for (int i = tid; i < 72*64; i += 256){
        float s = 0.f;
        #pragma unroll
        for (int sp = 0; sp < KSPLIT; sp++) s += g_kvP[sp][bh][i];
        g_kv16[(size_t)bh*72*64 + i] = __float2bfloat16_rn(s);
    }
}

// ---------------------------------------------------------------------------
// attn via MMA: per (bh, 128-t chunk): A = q[t][d], B = [kv;ksum][n][d]
// ---------------------------------------------------------------------------
__global__ void __launch_bounds__(256) attn_mma_kernel()
{
    __shared__ __nv_bfloat16 sQ[128*72];
    __shared__ __nv_bfloat16 sB[72*72];
    const int blk = blockIdx.x;
    const int tc  = blk % (TT/128);
    const int bh  = blk / (TT/128);
    const int b = bh / HH, h = bh % HH;
    const int tid = threadIdx.x;
    const int wid = tid >> 5, lane = tid & 31;
    const int g = lane >> 2, t4 = lane & 3;
    const uint32_t suQ = smem_u32(sQ);

    // B: copy reduced bf16 kv slab (u32-vectorized)
    const uint32_t* src = reinterpret_cast<const uint32_t*>(g_kv16 + (size_t)bh*72*64);
    uint32_t* sBu = reinterpret_cast<uint32_t*>(sB);
    for (int i = tid; i < 72*32; i += 256){
        int n = i >> 5, d2 = i & 31;
        sBu[n*36 + d2] = src[i];
    }

    const __nv_bfloat16* Qb = g_q16 + (size_t)(b*TT + tc*128)*CC + h*DD;
    #pragma unroll
    for (int r = 0; r < 4; r++){
        int i = tid + r*256;
        int row = i >> 3, cq = i & 7;
        CP_ASYNC16(suQ + (uint32_t)(row*72 + cq*8)*2, Qb + (size_t)row*CC + cq*8);
    }
    CP_COMMIT(); CP_WAIT0();
    __syncthreads();

    float acc[9][4];
    #pragma unroll
    for (int i = 0; i < 9; i++)
        #pragma unroll
        for (int e = 0; e < 4; e++) acc[i][e] = 0.f;

    const int m0 = wid * 16;
    #pragma unroll
    for (int s = 0; s < 4; s++){
        const int kb = s*16 + 2*t4;
        uint32_t ar[4], br[9][2];
        ar[0] = lds32(sQ + (m0+g  )*72 + kb);
        ar[1] = lds32(sQ + (m0+g+8)*72 + kb);
        ar[2] = lds32(sQ + (m0+g  )*72 + kb + 8);
        ar[3] = lds32(sQ + (m0+g+8)*72 + kb + 8);
        #pragma unroll
        for (int nf = 0; nf < 9; nf++){
            int c0 = nf*8 + g;
            br[nf][0] = lds32(sB + c0*72 + kb);
            br[nf][1] = lds32(sB + c0*72 + kb + 8);
        }
        #pragma unroll
        for (int nf = 0; nf < 9; nf++)
            mma_bf16(acc[nf], ar, br[nf]);
    }

    float zlo = __shfl_sync(0xffffffffu, acc[8][0], lane & ~3);
    float zhi = __shfl_sync(0xffffffffu, acc[8][2], lane & ~3);
    const float rlo = 1.f / (zlo + 1e-6f);
    const float rhi = 1.f / (zhi + 1e-6f);

    const size_t row0 = (size_t)(b*TT + tc*128 + m0 + g);
    #pragma unroll
    for (int nf = 0; nf < 8; nf++){
        const int n0 = h*DD + nf*8 + 2*t4;
        *reinterpret_cast<__nv_bfloat162*>(g_attn16 +  row0     *CC + n0)
            = __floats2bfloat162_rn(acc[nf][0]*rlo, acc[nf][1]*rlo);
        *reinterpret_cast<__nv_bfloat162*>(g_attn16 + (row0 + 8)*CC + n0)
            = __floats2bfloat162_rn(acc[nf][2]*rhi, acc[nf][3]*rhi);
    }
}

// ---------------------------------------------------------------------------
extern "C" void kernel_launch(void* const* d_in, const int* in_sizes, int n_in,
                              void* d_out, int out_size)
{
    const float* x  = (const float*)d_in[0];
    const float* Wq = (const float*)d_in[1];
    const float* bq = (const float*)d_in[2];
    const float* Wk = (const float*)d_in[3];
    const float* bk = (const float*)d_in[4];
    const float* Wv = (const float*)d_in[5];
    const float* bv = (const float*)d_in[6];
    const float* Wo = (const float*)d_in[7];
    const float* bo = (const float*)d_in[8];
    float* out = (float*)d_out;

    __nv_bfloat16 *gxt, *gq, *gkt, *gvt, *gattn, *gw;
    cudaGetSymbolAddress((void**)&gxt,  g_xt);
    cudaGetSymbolAddress((void**)&gq,   g_q16);
    cudaGetSymbolAddress((void**)&gkt,  g_kt);
    cudaGetSymbolAddress((void**)&gvt,  g_vt);
    cudaGetSymbolAddress((void**)&gattn,g_attn16);
    cudaGetSymbolAddress((void**)&gw,   g_w16);

    cudaFuncSetAttribute(gemm_qkv, cudaFuncAttributeMaxDynamicSharedMemorySize, GEMM_SMEM);
    cudaFuncSetAttribute(gemm_out, cudaFuncAttributeMaxDynamicSharedMemorySize, GEMM_SMEM);

    // 1. pack inputs to bf16
    transpose_round_kernel<<<dim3(TT/64, CC/64, BB), 256>>>(x);
    round_w4_kernel<<<dim3(CC*CC/1024, 4), 256>>>(Wq, Wk, Wv, Wo, gw);

    // 2. Q/K/V projections merged, z-fastest for A-tile L2 reuse
    gemm_qkv<<<dim3(3, BT/128, CC/128), 256, GEMM_SMEM>>>(
        gxt, gw, bq, bk, bv, gq, gkt, gvt);

    // 3. linear attention (tensor cores)
    kv_mma_kernel<<<BB*HH*KSPLIT, 256>>>();
    kv_reduce_kernel<<<BB*HH, 256>>>();
    attn_mma_kernel<<<BB*HH*(TT/128), 256>>>();

    // 4. output projection, n-fastest for A-tile L2 reuse
    gemm_out<<<dim3(CC/128, BT/128), 256, GEMM_SMEM>>>(
        gattn, gw + 3*(size_t)CC*CC, bo, x, out);
}

// round 15
// speedup vs baseline: 1.0618x; 1.0231x over previous
#include <cuda_runtime.h>
#include <cuda_bf16.h>
#include <math.h>
#include <stdint.h>

#define BB 4
#define CC 1024
#define TT 4096
#define HH 16
#define DD 64
#define BT (BB*TT)        // 16384
#define KSPLIT 8
#define NKCH 16           // K chunks of 64 per proj GEMM
#define SA 72             // GEMM smem row stride (bf16) — conflict-free for ldmatrix

// ---------------- scratch (alloc-free: __device__ globals) ----------------
__device__ __nv_bfloat16 g_xt [(size_t)BT*CC];     // xt[bt][c]
__device__ __nv_bfloat16 g_q16[(size_t)BT*CC];     // q[bt][c]
__device__ __nv_bfloat16 g_kt [(size_t)BB*CC*TT];  // k^T[b*CC+c][t]
__device__ __nv_bfloat16 g_vt [(size_t)BB*CC*TT];  // v^T[b*CC+c][t]
__device__ __nv_bfloat16 g_attn16[(size_t)BT*CC];  // attn[bt][c]
__device__ __nv_bfloat16 g_w16[(size_t)4*CC*CC];   // Wq,Wk,Wv,Wo bf16
// kv partials: [split][bh][n(72: 0..63=kv cols e, 64=ksum)][d(64)]
__device__ float g_kvP[KSPLIT][BB*HH][72*64];
__device__ __nv_bfloat16 g_kv16[(size_t)BB*HH*72*64];   // reduced kv, bf16

// ---------------- helpers ----------------
__device__ __forceinline__ uint32_t smem_u32(const void* p){
    uint32_t a;
    asm("{ .reg .u64 t; cvta.to.shared.u64 t, %1; cvt.u32.u64 %0, t; }" : "=r"(a) : "l"(p));
    return a;
}

#define CP_ASYNC16(saddr, gptr) \
    asm volatile("cp.async.cg.shared.global [%0], [%1], 16;" :: "r"(saddr), "l"(gptr))
#define CP_COMMIT() asm volatile("cp.async.commit_group;" ::: "memory")
#define CP_WAIT1()  asm volatile("cp.async.wait_group 1;" ::: "memory")
#define CP_WAIT0()  asm volatile("cp.async.wait_group 0;" ::: "memory")

// elu(v)+1 with fast exp: result is bf16-rounded downstream, so MUFU-based
// __expf (~2^-21 rel err) is exact after rounding to 8 mantissa bits.
__device__ __forceinline__ float elu1(float v){
    return (v > 0.f) ? (v + 1.f) : __expf(v);
}

// m16n8k16 bf16: D += A(16x16,row) * B(16x8, stored [n][k], k contiguous)
__device__ __forceinline__ void mma_bf16(float* c, const uint32_t* a, const uint32_t* b){
    asm volatile("mma.sync.aligned.m16n8k16.row.col.f32.bf16.bf16.f32 "
        "{%0,%1,%2,%3}, {%4,%5,%6,%7}, {%8,%9}, {%0,%1,%2,%3};"
        : "+f"(c[0]), "+f"(c[1]), "+f"(c[2]), "+f"(c[3])
        : "r"(a[0]), "r"(a[1]), "r"(a[2]), "r"(a[3]), "r"(b[0]), "r"(b[1]));
}
__device__ __forceinline__ uint32_t lds32(const __nv_bfloat16* p){
    return *reinterpret_cast<const uint32_t*>(p);
}
__device__ __forceinline__ void ldsm_x4(uint32_t* r, uint32_t addr){
    asm volatile("ldmatrix.sync.aligned.m8n8.x4.shared.b16 {%0,%1,%2,%3}, [%4];"
        : "=r"(r[0]), "=r"(r[1]), "=r"(r[2]), "=r"(r[3]) : "r"(addr));
}

#define STG (128*SA)                 // bf16 elements per operand per stage
#define GEMM_SMEM (3*2*STG*2)        // bytes = 110592  (2 blocks/SM: 221 KB <= 228)

// ---------------------------------------------------------------------------
// GEMM core (R14-proven): block 128x128, 8 warps (4m x 2n), warp tile 32x64,
// 3-stage cp.async, K-chunk 64 (4 k16 steps per chunk), ldmatrix.
// ---------------------------------------------------------------------------
struct GemmCtx {
    int tid, wid, lane, g, t4, wm, wn;
};

__device__ __forceinline__ void gemm_core(
    const __nv_bfloat16* __restrict__ Ab, const __nv_bfloat16* __restrict__ Bb,
    uint32_t su, const GemmCtx& c, float acc[2][8][4])
{
    const int rowA_l = (c.lane & 7) + 8*((c.lane >> 3) & 1);
    const int colA_l = 8*(c.lane >> 4);
    const int rowB_l = (c.lane & 7) + 8*(c.lane >> 4);
    const int colB_l = 8*((c.lane >> 3) & 1);

    auto load_stage = [&](int st, int kc){
        const uint32_t sa = su + (uint32_t)(st*2*STG)*2;
        const uint32_t sb = sa + (uint32_t)STG*2;
        const __nv_bfloat16* a = Ab + kc*64;
        const __nv_bfloat16* b = Bb + kc*64;
        #pragma unroll
        for (int r = 0; r < 4; r++){
            int i = c.tid + r*256;           // 1024 x 16B per operand
            int row = i >> 3, cq = i & 7;
            CP_ASYNC16(sa + (uint32_t)(row*SA + cq*8)*2, a + (size_t)row*CC + cq*8);
            CP_ASYNC16(sb + (uint32_t)(row*SA + cq*8)*2, b + (size_t)row*CC + cq*8);
        }
        CP_COMMIT();
    };

    load_stage(0, 0);
    load_stage(1, 1);

    for (int kc = 0; kc < NKCH; kc++){
        if (kc + 1 < NKCH) { CP_WAIT1(); } else { CP_WAIT0(); }
        __syncthreads();
        if (kc + 2 < NKCH) load_stage((kc+2) % 3, kc+2);

        const int st = kc % 3;
        const uint32_t sa = su + (uint32_t)(st*2*STG)*2;
        const uint32_t sb = sa + (uint32_t)STG*2;
        #pragma unroll
        for (int s = 0; s < 4; s++){
            const int sk = s*16;
            uint32_t ar[2][4], br[4][4];
            #pragma unroll
            for (int mf = 0; mf < 2; mf++){
                int ml = c.wm*32 + mf*16;
                ldsm_x4(ar[mf], sa + (uint32_t)((ml + rowA_l)*SA + sk + colA_l)*2);
            }
            #pragma unroll
            for (int nf2 = 0; nf2 < 4; nf2++){
                int nl = c.wn*64 + nf2*16;
                ldsm_x4(br[nf2], sb + (uint32_t)((nl + rowB_l)*SA + sk + colB_l)*2);
            }
            #pragma unroll
            for (int mf = 0; mf < 2; mf++)
                #pragma unroll
                for (int nf = 0; nf < 8; nf++)
                    mma_bf16(acc[mf][nf], ar[mf], &br[nf >> 1][(nf & 1)*2]);
        }
    }
}

// ---------------------------------------------------------------------------
// Merged Q/K/V projection. Grid = (3, BT/128, CC/128): z FASTEST so the 24
// consecutive blocks (3 z x 8 n) sharing one A tile run in the same wave.
// ---------------------------------------------------------------------------
__global__ void __launch_bounds__(256, 2)
gemm_qkv(const __nv_bfloat16* __restrict__ A, const __nv_bfloat16* __restrict__ W,
         const float* __restrict__ bq, const float* __restrict__ bk,
         const float* __restrict__ bv,
         __nv_bfloat16* __restrict__ outq, __nv_bfloat16* __restrict__ outkt,
         __nv_bfloat16* __restrict__ outvt)
{
    extern __shared__ __nv_bfloat16 sm[];
    const uint32_t su = smem_u32(sm);
    GemmCtx c;
    c.tid = threadIdx.x; c.wid = c.tid >> 5; c.lane = c.tid & 31;
    c.g = c.lane >> 2; c.t4 = c.lane & 3;
    c.wm = c.wid >> 1;  c.wn = c.wid & 1;
    const int z  = blockIdx.x;
    const int bm = blockIdx.y * 128;
    const int bn = blockIdx.z * 128;

    const float* bias = (z == 0) ? bq : (z == 1) ? bk : bv;
    const __nv_bfloat16* Ab = A + (size_t)bm * CC;
    const __nv_bfloat16* Bb = W + (size_t)z*CC*CC + (size_t)bn * CC;

    float acc[2][8][4];
    #pragma unroll
    for (int i = 0; i < 2; i++)
        #pragma unroll
        for (int j = 0; j < 8; j++)
            #pragma unroll
            for (int e = 0; e < 4; e++) acc[i][j][e] = 0.f;

    gemm_core(Ab, Bb, su, c, acc);

    const bool act = (z != 2);
    #pragma unroll
    for (int mf = 0; mf < 2; mf++){
        const int m0 = bm + c.wm*32 + mf*16 + c.g;
        #pragma unroll
        for (int nf = 0; nf < 8; nf++){
            const int n0 = bn + c.wn*64 + nf*8 + c.t4*2;
            const float b0 = bias[n0], b1 = bias[n0+1];
            float v00 = acc[mf][nf][0] + b0;
            float v01 = acc[mf][nf][1] + b1;
            float v10 = acc[mf][nf][2] + b0;
            float v11 = acc[mf][nf][3] + b1;
            if (act){
                v00 = elu1(v00);
                v01 = elu1(v01);
                v10 = elu1(v10);
                v11 = elu1(v11);
            }
            if (z == 0){
                *reinterpret_cast<__nv_bfloat162*>(outq + (size_t) m0   *CC + n0)
                    = __floats2bfloat162_rn(v00, v01);
                *reinterpret_cast<__nv_bfloat162*>(outq + (size_t)(m0+8)*CC + n0)
                    = __floats2bfloat162_rn(v10, v11);
            } else {
                __nv_bfloat16* o = (z == 1) ? outkt : outvt;
                const int b = m0 / TT, t = m0 % TT;
                size_t r0i = ((size_t)b*CC + n0)*TT + t;
                size_t r1i = r0i + TT;
                o[r0i]     = __float2bfloat16_rn(v00);
                o[r1i]     = __float2bfloat16_rn(v01);
                o[r0i + 8] = __float2bfloat16_rn(v10);
                o[r1i + 8] = __float2bfloat16_rn(v11);
            }
        }
    }
}

// ---------------------------------------------------------------------------
// Output projection + bias + residual + transpose -> fp32 out[b][n][t]
// Grid = (CC/128, BT/128): n FASTEST so blocks sharing an A tile co-run.
// ---------------------------------------------------------------------------
__global__ void __launch_bounds__(256, 2)
gemm_out(const __nv_bfloat16* __restrict__ A, const __nv_bfloat16* __restrict__ W,
         const float* __restrict__ bias, const float* __restrict__ resid,
         float* __restrict__ outf)
{
    extern __shared__ __nv_bfloat16 sm[];
    const uint32_t su = smem_u32(sm);
    GemmCtx c;
    c.tid = threadIdx.x; c.wid = c.tid >> 5; c.lane = c.tid & 31;
    c.g = c.lane >> 2; c.t4 = c.lane & 3;
    c.wm = c.wid >> 1;  c.wn = c.wid & 1;
    const int bn = blockIdx.x * 128;
    const int bm = blockIdx.y * 128;

    const __nv_bfloat16* Ab = A + (size_t)bm * CC;
    const __nv_bfloat16* Bb = W + (size_t)bn * CC;

    float acc[2][8][4];
    #pragma unroll
    for (int i = 0; i < 2; i++)
        #pragma unroll
        for (int j = 0; j < 8; j++)
            #pragma unroll
            for (int e = 0; e < 4; e++) acc[i][j][e] = 0.f;

    gemm_core(Ab, Bb, su, c, acc);

    #pragma unroll
    for (int mf = 0; mf < 2; mf++){
        const int m0 = bm + c.wm*32 + mf*16 + c.g;
        const int b = m0 / TT, t = m0 % TT;
        #pragma unroll
        for (int nf = 0; nf < 8; nf++){
            const int n0 = bn + c.wn*64 + nf*8 + c.t4*2;
            size_t i00 = (size_t)b*CC*TT + (size_t)n0*TT + t;
            size_t i01 = i00 + TT;
            outf[i00]     = acc[mf][nf][0] + bias[n0]   + resid[i00];
            outf[i01]     = acc[mf][nf][1] + bias[n0+1] + resid[i01];
            outf[i00 + 8] = acc[mf][nf][2] + bias[n0]   + resid[i00 + 8];
            outf[i01 + 8] = acc[mf][nf][3] + bias[n0+1] + resid[i01 + 8];
        }
    }
}

// ---------------------------------------------------------------------------
// x[b,c,t] -> g_xt[b*T+t][c] bf16. 64x64 tiles, float4 loads, uint4 stores.
// ---------------------------------------------------------------------------
__global__ void __launch_bounds__(256) transpose_round_kernel(const float* __restrict__ x)
{
    __shared__ float tile[64][65];
    const int t0 = blockIdx.x * 64;
    const int c0 = blockIdx.y * 64;
    const int b  = blockIdx.z;
    const int tid = threadIdx.x;
    const int row = tid >> 2;            // c-row within tile
    const int q   = tid & 3;

    const float* src = x + (size_t)b*CC*TT + (size_t)(c0+row)*TT + t0 + q*16;
    #pragma unroll
    for (int j = 0; j < 4; j++){
        float4 v = *reinterpret_cast<const float4*>(src + j*4);
        tile[row][q*16 + j*4 + 0] = v.x;
        tile[row][q*16 + j*4 + 1] = v.y;
        tile[row][q*16 + j*4 + 2] = v.z;
        tile[row][q*16 + j*4 + 3] = v.w;
    }
    __syncthreads();

    uint32_t* dst = reinterpret_cast<uint32_t*>(
        g_xt + (size_t)(b*TT + t0 + row)*CC + c0);
    uint32_t tmp[8];
    #pragma unroll
    for (int j = 0; j < 8; j++){
        int cu = q*8 + j;                 // u32 column
        __nv_bfloat162 p = __floats2bfloat162_rn(tile[2*cu][row], tile[2*cu+1][row]);
        tmp[j] = *reinterpret_cast<uint32_t*>(&p);
    }
    *reinterpret_cast<uint4*>(dst + q*8)     = make_uint4(tmp[0], tmp[1], tmp[2], tmp[3]);
    *reinterpret_cast<uint4*>(dst + q*8 + 4) = make_uint4(tmp[4], tmp[5], tmp[6], tmp[7]);
}

// all 4 weights in one launch, vectorized x4: blockIdx.y selects the matrix
__global__ void round_w4_kernel(const float* __restrict__ w0, const float* __restrict__ w1,
                                const float* __restrict__ w2, const float* __restrict__ w3,
                                __nv_bfloat16* __restrict__ dst)
{
    const float* w = (blockIdx.y == 0) ? w0 : (blockIdx.y == 1) ? w1
                   : (blockIdx.y == 2) ? w2 : w3;
    int i = (blockIdx.x * 256 + threadIdx.x) * 4;
    float4 v = *reinterpret_cast<const float4*>(w + i);
    __nv_bfloat162 lo = __floats2bfloat162_rn(v.x, v.y);
    __nv_bfloat162 hi = __floats2bfloat162_rn(v.z, v.w);
    uint2 p = make_uint2(*reinterpret_cast<uint32_t*>(&lo),
                         *reinterpret_cast<uint32_t*>(&hi));
    *reinterpret_cast<uint2*>(dst + (size_t)blockIdx.y*CC*CC + i) = p;
}

// ---------------------------------------------------------------------------
// kv via MMA: per (bh, split): A = k^T[d][t], B = [v^T; ones][n][t]
// ---------------------------------------------------------------------------
__global__ void __launch_bounds__(256) kv_mma_kernel()
{
    __shared__ __nv_bfloat16 sA[2][64*72];
    __shared__ __nv_bfloat16 sB[2][72*72];
    const int blk = blockIdx.x;
    const int sp  = blk % KSPLIT;
    const int bh  = blk / KSPLIT;
    const int b = bh / HH, h = bh % HH;
    const int tid = threadIdx.x;
    const int wid = tid >> 5, lane = tid & 31;
    const int g = lane >> 2, t4 = lane & 3;
    const int wm = wid >> 2, wn = wid & 3;
    const int nt = (wn == 3) ? 3 : 2;

    const uint32_t suA[2] = {smem_u32(sA[0]), smem_u32(sA[1])};
    const uint32_t suB[2] = {smem_u32(sB[0]), smem_u32(sB[1])};

    for (int st = 0; st < 2; st++)
        for (int i = tid; i < 8*64; i += 256){
            int rr = i >> 6, cx = i & 63;
            sB[st][(64+rr)*72 + cx] = __float2bfloat16((rr == 0) ? 1.f : 0.f);
        }

    float acc[2][3][4];
    #pragma unroll
    for (int i = 0; i < 2; i++)
        #pragma unroll
        for (int j = 0; j < 3; j++)
            #pragma unroll
            for (int e = 0; e < 4; e++) acc[i][j][e] = 0.f;

    const __nv_bfloat16* Kb = g_kt + ((size_t)b*CC + h*DD)*TT + sp*(TT/KSPLIT);
    const __nv_bfloat16* Vb = g_vt + ((size_t)b*CC + h*DD)*TT + sp*(TT/KSPLIT);

    auto load_stage = [&](int st, int tc){
        #pragma unroll
        for (int r = 0; r < 2; r++){
            int i = tid + r*256;
            int row = i >> 3, cq = i & 7;
            CP_ASYNC16(suA[st] + (uint32_t)(row*72 + cq*8)*2,
                       Kb + (size_t)row*TT + tc*64 + cq*8);
            CP_ASYNC16(suB[st] + (uint32_t)(row*72 + cq*8)*2,
                       Vb + (size_t)row*TT + tc*64 + cq*8);
        }
    };

    const int NT = (TT/KSPLIT)/64;   // 8
    load_stage(0, 0); CP_COMMIT();

    for (int tc = 0; tc < NT; tc++){
        const int cur = tc & 1;
        if (tc + 1 < NT){ load_stage(cur^1, tc+1); CP_COMMIT(); CP_WAIT1(); }
        else            { CP_WAIT0(); }
        __syncthreads();

        const __nv_bfloat16* pa = sA[cur];
        const __nv_bfloat16* pb = sB[cur];
        #pragma unroll
        for (int s = 0; s < 4; s++){
            const int kb = s*16 + 2*t4;
            uint32_t ar[2][4], br[3][2];
            #pragma unroll
            for (int mf = 0; mf < 2; mf++){
                int r0 = wm*32 + mf*16 + g;
                ar[mf][0] = lds32(pa +  r0   *72 + kb);
                ar[mf][1] = lds32(pa + (r0+8)*72 + kb);
                ar[mf][2] = lds32(pa +  r0   *72 + kb + 8);
                ar[mf][3] = lds32(pa + (r0+8)*72 + kb + 8);
            }
            #pragma unroll
            for (int nf = 0; nf < 3; nf++){
                if (nf < nt){
                    int c0 = (nf == 2) ? (64 + g) : (wn*16 + nf*8 + g);
                    br[nf][0] = lds32(pb + c0*72 + kb);
                    br[nf][1] = lds32(pb + c0*72 + kb + 8);
                }
            }
            #pragma unroll
            for (int mf = 0; mf < 2; mf++)
                #pragma unroll
                for (int nf = 0; nf < 3; nf++)
                    if (nf < nt) mma_bf16(acc[mf][nf], ar[mf], br[nf]);
        }
        __syncthreads();
    }

    float* dst = g_kvP[sp][bh];
    #pragma unroll
    for (int mf = 0; mf < 2; mf++){
        const int m0 = wm*32 + mf*16 + g;
        #pragma unroll
        for (int nf = 0; nf < 3; nf++){
            if (nf >= nt) continue;
            const int n0 = (nf == 2) ? (64 + 2*t4) : (wn*16 + nf*8 + 2*t4);
            dst[(n0  )*64 + m0    ] = acc[mf][nf][0];
            dst[(n0+1)*64 + m0    ] = acc[mf][nf][1];
            dst[(n0  )*64 + m0 + 8] = acc[mf][nf][2];
            dst[(n0+1)*64 + m0 + 8] = acc[mf][nf][3];
        }
    }
}

// ---------------------------------------------------------------------------
// reduce KSPLIT kv partials -> bf16 slab g_kv16[bh][72*64]
// ---------------------------------------------------------------------------
__global__ void __launch_bounds__(256) kv_reduce_kernel()
{
    const int bh = blockIdx.x;
    const int tid = threadIdx.x;
    for (int i = tid; i < 72*64; i += 256){
        float s = 0.f;
        #pragma unroll
        for (int sp = 0; sp < KSPLIT; sp++) s += g_kvP[sp][bh][i];
        g_kv16[(size_t)bh*72*64 + i] = __float2bfloat16_rn(s);
    }
}

// ---------------------------------------------------------------------------
// attn via MMA: per (bh, 128-t chunk): A = q[t][d], B = [kv;ksum][n][d]
// ---------------------------------------------------------------------------
__global__ void __launch_bounds__(256) attn_mma_kernel()
{
    __shared__ __nv_bfloat16 sQ[128*72];
    __shared__ __nv_bfloat16 sB[72*72];
    const int blk = blockIdx.x;
    const int tc  = blk % (TT/128);
    const int bh  = blk / (TT/128);
    const int b = bh / HH, h = bh % HH;
    const int tid = threadIdx.x;
    const int wid = tid >> 5, lane = tid & 31;
    const int g = lane >> 2, t4 = lane & 3;
    const uint32_t suQ = smem_u32(sQ);

    // B: copy reduced bf16 kv slab (u32-vectorized)
    const uint32_t* src = reinterpret_cast<const uint32_t*>(g_kv16 + (size_t)bh*72*64);
    uint32_t* sBu = reinterpret_cast<uint32_t*>(sB);
    for (int i = tid; i < 72*32; i += 256){
        int n = i >> 5, d2 = i & 31;
        sBu[n*36 + d2] = src[i];
    }

    const __nv_bfloat16* Qb = g_q16 + (size_t)(b*TT + tc*128)*CC + h*DD;
    #pragma unroll
    for (int r = 0; r < 4; r++){
        int i = tid + r*256;
        int row = i >> 3, cq = i & 7;
        CP_ASYNC16(suQ + (uint32_t)(row*72 + cq*8)*2, Qb + (size_t)row*CC + cq*8);
    }
    CP_COMMIT(); CP_WAIT0();
    __syncthreads();

    float acc[9][4];
    #pragma unroll
    for (int i = 0; i < 9; i++)
        #pragma unroll
        for (int e = 0; e < 4; e++) acc[i][e] = 0.f;

    const int m0 = wid * 16;
    #pragma unroll
    for (int s = 0; s < 4; s++){
        const int kb = s*16 + 2*t4;
        uint32_t ar[4], br[9][2];
        ar[0] = lds32(sQ + (m0+g  )*72 + kb);
        ar[1] = lds32(sQ + (m0+g+8)*72 + kb);
        ar[2] = lds32(sQ + (m0+g  )*72 + kb + 8);
        ar[3] = lds32(sQ + (m0+g+8)*72 + kb + 8);
        #pragma unroll
        for (int nf = 0; nf < 9; nf++){
            int c0 = nf*8 + g;
            br[nf][0] = lds32(sB + c0*72 + kb);
            br[nf][1] = lds32(sB + c0*72 + kb + 8);
        }
        #pragma unroll
        for (int nf = 0; nf < 9; nf++)
            mma_bf16(acc[nf], ar, br[nf]);
    }

    float zlo = __shfl_sync(0xffffffffu, acc[8][0], lane & ~3);
    float zhi = __shfl_sync(0xffffffffu, acc[8][2], lane & ~3);
    const float rlo = 1.f / (zlo + 1e-6f);
    const float rhi = 1.f / (zhi + 1e-6f);

    const size_t row0 = (size_t)(b*TT + tc*128 + m0 + g);
    #pragma unroll
    for (int nf = 0; nf < 8; nf++){
        const int n0 = h*DD + nf*8 + 2*t4;
        *reinterpret_cast<__nv_bfloat162*>(g_attn16 +  row0     *CC + n0)
            = __floats2bfloat162_rn(acc[nf][0]*rlo, acc[nf][1]*rlo);
        *reinterpret_cast<__nv_bfloat162*>(g_attn16 + (row0 + 8)*CC + n0)
            = __floats2bfloat162_rn(acc[nf][2]*rhi, acc[nf][3]*rhi);
    }
}

// ---------------------------------------------------------------------------
extern "C" void kernel_launch(void* const* d_in, const int* in_sizes, int n_in,
                              void* d_out, int out_size)
{
    const float* x  = (const float*)d_in[0];
    const float* Wq = (const float*)d_in[1];
    const float* bq = (const float*)d_in[2];
    const float* Wk = (const float*)d_in[3];
    const float* bk = (const float*)d_in[4];
    const float* Wv = (const float*)d_in[5];
    const float* bv = (const float*)d_in[6];
    const float* Wo = (const float*)d_in[7];
    const float* bo = (const float*)d_in[8];
    float* out = (float*)d_out;

    __nv_bfloat16 *gxt, *gq, *gkt, *gvt, *gattn, *gw;
    cudaGetSymbolAddress((void**)&gxt,  g_xt);
    cudaGetSymbolAddress((void**)&gq,   g_q16);
    cudaGetSymbolAddress((void**)&gkt,  g_kt);
    cudaGetSymbolAddress((void**)&gvt,  g_vt);
    cudaGetSymbolAddress((void**)&gattn,g_attn16);
    cudaGetSymbolAddress((void**)&gw,   g_w16);

    cudaFuncSetAttribute(gemm_qkv, cudaFuncAttributeMaxDynamicSharedMemorySize, GEMM_SMEM);
    cudaFuncSetAttribute(gemm_out, cudaFuncAttributeMaxDynamicSharedMemorySize, GEMM_SMEM);

    // 1. pack inputs to bf16
    transpose_round_kernel<<<dim3(TT/64, CC/64, BB), 256>>>(x);
    round_w4_kernel<<<dim3(CC*CC/1024, 4), 256>>>(Wq, Wk, Wv, Wo, gw);

    // 2. Q/K/V projections merged, z-fastest for A-tile L2 reuse
    gemm_qkv<<<dim3(3, BT/128, CC/128), 256, GEMM_SMEM>>>(
        gxt, gw, bq, bk, bv, gq, gkt, gvt);

    // 3. linear attention (tensor cores)
    kv_mma_kernel<<<BB*HH*KSPLIT, 256>>>();
    kv_reduce_kernel<<<BB*HH, 256>>>();
    attn_mma_kernel<<<BB*HH*(TT/128), 256>>>();

    // 4. output projection, n-fastest for A-tile L2 reuse
    gemm_out<<<dim3(CC/128, BT/128), 256, GEMM_SMEM>>>(
        gattn, gw + 3*(size_t)CC*CC, bo, x, out);
}

// round 16
// speedup vs baseline: 1.0733x; 1.0108x over previous
#include <cuda_runtime.h>
#include <cuda_bf16.h>
#include <math.h>
#include <stdint.h>

#define BB 4
#define CC 1024
#define TT 4096
#define HH 16
#define DD 64
#define BT (BB*TT)        // 16384
#define KSPLIT 8
#define NKCH 16           // K chunks of 64 per proj GEMM
#define SA 72             // GEMM smem row stride (bf16) — conflict-free for ldmatrix

// ---------------- scratch (alloc-free: __device__ globals) ----------------
__device__ __nv_bfloat16 g_xt [(size_t)BT*CC];     // xt[bt][c]
__device__ __nv_bfloat16 g_q16[(size_t)BT*CC];     // q[bt][c]
__device__ __nv_bfloat16 g_kt [(size_t)BB*CC*TT];  // k^T[b*CC+c][t]
__device__ __nv_bfloat16 g_vt [(size_t)BB*CC*TT];  // v^T[b*CC+c][t]
__device__ __nv_bfloat16 g_attn16[(size_t)BT*CC];  // attn[bt][c]
__device__ __nv_bfloat16 g_w16[(size_t)4*CC*CC];   // Wq,Wk,Wv,Wo bf16
// kv partials: [split][bh][n(72: 0..63=kv cols e, 64=ksum)][d(64)]
__device__ float g_kvP[KSPLIT][BB*HH][72*64];
__device__ __nv_bfloat16 g_kv16[(size_t)BB*HH*72*64];   // reduced kv, bf16

// ---------------- helpers ----------------
__device__ __forceinline__ uint32_t smem_u32(const void* p){
    uint32_t a;
    asm("{ .reg .u64 t; cvta.to.shared.u64 t, %1; cvt.u32.u64 %0, t; }" : "=r"(a) : "l"(p));
    return a;
}

#define CP_ASYNC16(saddr, gptr) \
    asm volatile("cp.async.cg.shared.global [%0], [%1], 16;" :: "r"(saddr), "l"(gptr))
#define CP_COMMIT() asm volatile("cp.async.commit_group;" ::: "memory")
#define CP_WAIT1()  asm volatile("cp.async.wait_group 1;" ::: "memory")
#define CP_WAIT0()  asm volatile("cp.async.wait_group 0;" ::: "memory")

// elu(v)+1 with fast exp: result is bf16-rounded downstream, so MUFU-based
// __expf (~2^-21 rel err) is exact after rounding to 8 mantissa bits.
__device__ __forceinline__ float elu1(float v){
    return (v > 0.f) ? (v + 1.f) : __expf(v);
}

// m16n8k16 bf16: D += A(16x16,row) * B(16x8, stored [n][k], k contiguous)
__device__ __forceinline__ void mma_bf16(float* c, const uint32_t* a, const uint32_t* b){
    asm volatile("mma.sync.aligned.m16n8k16.row.col.f32.bf16.bf16.f32 "
        "{%0,%1,%2,%3}, {%4,%5,%6,%7}, {%8,%9}, {%0,%1,%2,%3};"
        : "+f"(c[0]), "+f"(c[1]), "+f"(c[2]), "+f"(c[3])
        : "r"(a[0]), "r"(a[1]), "r"(a[2]), "r"(a[3]), "r"(b[0]), "r"(b[1]));
}
__device__ __forceinline__ uint32_t lds32(const __nv_bfloat16* p){
    return *reinterpret_cast<const uint32_t*>(p);
}
__device__ __forceinline__ void ldsm_x4(uint32_t* r, uint32_t addr){
    asm volatile("ldmatrix.sync.aligned.m8n8.x4.shared.b16 {%0,%1,%2,%3}, [%4];"
        : "=r"(r[0]), "=r"(r[1]), "=r"(r[2]), "=r"(r[3]) : "r"(addr));
}

#define STG (128*SA)                 // bf16 elements per operand per stage
#define GEMM_SMEM (3*2*STG*2)        // bytes = 110592  (2 blocks/SM: 221 KB <= 228)

// ---------------------------------------------------------------------------
// GEMM core (R14/R15-proven): block 128x128, 8 warps (4m x 2n), warp tile
// 32x64, 3-stage cp.async, K-chunk 64 (4 k16 steps per chunk), ldmatrix.
// ---------------------------------------------------------------------------
struct GemmCtx {
    int tid, wid, lane, g, t4, wm, wn;
};

__device__ __forceinline__ void gemm_core(
    const __nv_bfloat16* __restrict__ Ab, const __nv_bfloat16* __restrict__ Bb,
    uint32_t su, const GemmCtx& c, float acc[2][8][4])
{
    const int rowA_l = (c.lane & 7) + 8*((c.lane >> 3) & 1);
    const int colA_l = 8*(c.lane >> 4);
    const int rowB_l = (c.lane & 7) + 8*(c.lane >> 4);
    const int colB_l = 8*((c.lane >> 3) & 1);

    auto load_stage = [&](int st, int kc){
        const uint32_t sa = su + (uint32_t)(st*2*STG)*2;
        const uint32_t sb = sa + (uint32_t)STG*2;
        const __nv_bfloat16* a = Ab + kc*64;
        const __nv_bfloat16* b = Bb + kc*64;
        #pragma unroll
        for (int r = 0; r < 4; r++){
            int i = c.tid + r*256;           // 1024 x 16B per operand
            int row = i >> 3, cq = i & 7;
            CP_ASYNC16(sa + (uint32_t)(row*SA + cq*8)*2, a + (size_t)row*CC + cq*8);
            CP_ASYNC16(sb + (uint32_t)(row*SA + cq*8)*2, b + (size_t)row*CC + cq*8);
        }
        CP_COMMIT();
    };

    load_stage(0, 0);
    load_stage(1, 1);

    for (int kc = 0; kc < NKCH; kc++){
        if (kc + 1 < NKCH) { CP_WAIT1(); } else { CP_WAIT0(); }
        __syncthreads();
        if (kc + 2 < NKCH) load_stage((kc+2) % 3, kc+2);

        const int st = kc % 3;
        const uint32_t sa = su + (uint32_t)(st*2*STG)*2;
        const uint32_t sb = sa + (uint32_t)STG*2;
        #pragma unroll
        for (int s = 0; s < 4; s++){
            const int sk = s*16;
            uint32_t ar[2][4], br[4][4];
            #pragma unroll
            for (int mf = 0; mf < 2; mf++){
                int ml = c.wm*32 + mf*16;
                ldsm_x4(ar[mf], sa + (uint32_t)((ml + rowA_l)*SA + sk + colA_l)*2);
            }
            #pragma unroll
            for (int nf2 = 0; nf2 < 4; nf2++){
                int nl = c.wn*64 + nf2*16;
                ldsm_x4(br[nf2], sb + (uint32_t)((nl + rowB_l)*SA + sk + colB_l)*2);
            }
            #pragma unroll
            for (int mf = 0; mf < 2; mf++)
                #pragma unroll
                for (int nf = 0; nf < 8; nf++)
                    mma_bf16(acc[mf][nf], ar[mf], &br[nf >> 1][(nf & 1)*2]);
        }
    }
}

// ---------------------------------------------------------------------------
// Merged Q/K/V projection. Grid = (3, BT/128, CC/128): z FASTEST so the 24
// consecutive blocks (3 z x 8 n) sharing one A tile run in the same wave.
// ---------------------------------------------------------------------------
__global__ void __launch_bounds__(256, 2)
gemm_qkv(const __nv_bfloat16* __restrict__ A, const __nv_bfloat16* __restrict__ W,
         const float* __restrict__ bq, const float* __restrict__ bk,
         const float* __restrict__ bv,
         __nv_bfloat16* __restrict__ outq, __nv_bfloat16* __restrict__ outkt,
         __nv_bfloat16* __restrict__ outvt)
{
    extern __shared__ __nv_bfloat16 sm[];
    const uint32_t su = smem_u32(sm);
    GemmCtx c;
    c.tid = threadIdx.x; c.wid = c.tid >> 5; c.lane = c.tid & 31;
    c.g = c.lane >> 2; c.t4 = c.lane & 3;
    c.wm = c.wid >> 1;  c.wn = c.wid & 1;
    const int z  = blockIdx.x;
    const int bm = blockIdx.y * 128;
    const int bn = blockIdx.z * 128;

    const float* bias = (z == 0) ? bq : (z == 1) ? bk : bv;
    const __nv_bfloat16* Ab = A + (size_t)bm * CC;
    const __nv_bfloat16* Bb = W + (size_t)z*CC*CC + (size_t)bn * CC;

    float acc[2][8][4];
    #pragma unroll
    for (int i = 0; i < 2; i++)
        #pragma unroll
        for (int j = 0; j < 8; j++)
            #pragma unroll
            for (int e = 0; e < 4; e++) acc[i][j][e] = 0.f;

    gemm_core(Ab, Bb, su, c, acc);

    const bool act = (z != 2);
    #pragma unroll
    for (int mf = 0; mf < 2; mf++){
        const int m0 = bm + c.wm*32 + mf*16 + c.g;
        #pragma unroll
        for (int nf = 0; nf < 8; nf++){
            const int n0 = bn + c.wn*64 + nf*8 + c.t4*2;
            const float b0 = bias[n0], b1 = bias[n0+1];
            float v00 = acc[mf][nf][0] + b0;
            float v01 = acc[mf][nf][1] + b1;
            float v10 = acc[mf][nf][2] + b0;
            float v11 = acc[mf][nf][3] + b1;
            if (act){
                v00 = elu1(v00);
                v01 = elu1(v01);
                v10 = elu1(v10);
                v11 = elu1(v11);
            }
            if (z == 0){
                *reinterpret_cast<__nv_bfloat162*>(outq + (size_t) m0   *CC + n0)
                    = __floats2bfloat162_rn(v00, v01);
                *reinterpret_cast<__nv_bfloat162*>(outq + (size_t)(m0+8)*CC + n0)
                    = __floats2bfloat162_rn(v10, v11);
            } else {
                __nv_bfloat16* o = (z == 1) ? outkt : outvt;
                const int b = m0 / TT, t = m0 % TT;
                size_t r0i = ((size_t)b*CC + n0)*TT + t;
                size_t r1i = r0i + TT;
                o[r0i]     = __float2bfloat16_rn(v00);
                o[r1i]     = __float2bfloat16_rn(v01);
                o[r0i + 8] = __float2bfloat16_rn(v10);
                o[r1i + 8] = __float2bfloat16_rn(v11);
            }
        }
    }
}

// ---------------------------------------------------------------------------
// Output projection + bias + residual + transpose -> fp32 out[b][n][t]
// Grid = (CC/128, BT/128): n FASTEST so blocks sharing an A tile co-run.
// ---------------------------------------------------------------------------
__global__ void __launch_bounds__(256, 2)
gemm_out(const __nv_bfloat16* __restrict__ A, const __nv_bfloat16* __restrict__ W,
         const float* __restrict__ bias, const float* __restrict__ resid,
         float* __restrict__ outf)
{
    extern __shared__ __nv_bfloat16 sm[];
    const uint32_t su = smem_u32(sm);
    GemmCtx c;
    c.tid = threadIdx.x; c.wid = c.tid >> 5; c.lane = c.tid & 31;
    c.g = c.lane >> 2; c.t4 = c.lane & 3;
    c.wm = c.wid >> 1;  c.wn = c.wid & 1;
    const int bn = blockIdx.x * 128;
    const int bm = blockIdx.y * 128;

    const __nv_bfloat16* Ab = A + (size_t)bm * CC;
    const __nv_bfloat16* Bb = W + (size_t)bn * CC;

    float acc[2][8][4];
    #pragma unroll
    for (int i = 0; i < 2; i++)
        #pragma unroll
        for (int j = 0; j < 8; j++)
            #pragma unroll
            for (int e = 0; e < 4; e++) acc[i][j][e] = 0.f;

    gemm_core(Ab, Bb, su, c, acc);

    #pragma unroll
    for (int mf = 0; mf < 2; mf++){
        const int m0 = bm + c.wm*32 + mf*16 + c.g;
        const int b = m0 / TT, t = m0 % TT;
        #pragma unroll
        for (int nf = 0; nf < 8; nf++){
            const int n0 = bn + c.wn*64 + nf*8 + c.t4*2;
            size_t i00 = (size_t)b*CC*TT + (size_t)n0*TT + t;
            size_t i01 = i00 + TT;
            outf[i00]     = acc[mf][nf][0] + bias[n0]   + resid[i00];
            outf[i01]     = acc[mf][nf][1] + bias[n0+1] + resid[i01];
            outf[i00 + 8] = acc[mf][nf][2] + bias[n0]   + resid[i00 + 8];
            outf[i01 + 8] = acc[mf][nf][3] + bias[n0+1] + resid[i01 + 8];
        }
    }
}

// ---------------------------------------------------------------------------
// x[b,c,t] -> g_xt[b*T+t][c] bf16. 64x64 tiles, float4 loads, uint4 stores.
// ---------------------------------------------------------------------------
__global__ void __launch_bounds__(256) transpose_round_kernel(const float* __restrict__ x)
{
    __shared__ float tile[64][65];
    const int t0 = blockIdx.x * 64;
    const int c0 = blockIdx.y * 64;
    const int b  = blockIdx.z;
    const int tid = threadIdx.x;
    const int row = tid >> 2;            // c-row within tile
    const int q   = tid & 3;

    const float* src = x + (size_t)b*CC*TT + (size_t)(c0+row)*TT + t0 + q*16;
    #pragma unroll
    for (int j = 0; j < 4; j++){
        float4 v = *reinterpret_cast<const float4*>(src + j*4);
        tile[row][q*16 + j*4 + 0] = v.x;
        tile[row][q*16 + j*4 + 1] = v.y;
        tile[row][q*16 + j*4 + 2] = v.z;
        tile[row][q*16 + j*4 + 3] = v.w;
    }
    __syncthreads();

    uint32_t* dst = reinterpret_cast<uint32_t*>(
        g_xt + (size_t)(b*TT + t0 + row)*CC + c0);
    uint32_t tmp[8];
    #pragma unroll
    for (int j = 0; j < 8; j++){
        int cu = q*8 + j;                 // u32 column
        __nv_bfloat162 p = __floats2bfloat162_rn(tile[2*cu][row], tile[2*cu+1][row]);
        tmp[j] = *reinterpret_cast<uint32_t*>(&p);
    }
    *reinterpret_cast<uint4*>(dst + q*8)     = make_uint4(tmp[0], tmp[1], tmp[2], tmp[3]);
    *reinterpret_cast<uint4*>(dst + q*8 + 4) = make_uint4(tmp[4], tmp[5], tmp[6], tmp[7]);
}

// all 4 weights in one launch, vectorized x4: blockIdx.y selects the matrix
__global__ void round_w4_kernel(const float* __restrict__ w0, const float* __restrict__ w1,
                                const float* __restrict__ w2, const float* __restrict__ w3,
                                __nv_bfloat16* __restrict__ dst)
{
    const float* w = (blockIdx.y == 0) ? w0 : (blockIdx.y == 1) ? w1
                   : (blockIdx.y == 2) ? w2 : w3;
    int i = (blockIdx.x * 256 + threadIdx.x) * 4;
    float4 v = *reinterpret_cast<const float4*>(w + i);
    __nv_bfloat162 lo = __floats2bfloat162_rn(v.x, v.y);
    __nv_bfloat162 hi = __floats2bfloat162_rn(v.z, v.w);
    uint2 p = make_uint2(*reinterpret_cast<uint32_t*>(&lo),
                         *reinterpret_cast<uint32_t*>(&hi));
    *reinterpret_cast<uint2*>(dst + (size_t)blockIdx.y*CC*CC + i) = p;
}

// ---------------------------------------------------------------------------
// kv via MMA: per (bh, split): A = k^T[d][t], B = [v^T; ones][n][t]
// 3-stage cp.async pipeline (DRAM-latency-bound kernel).
// ---------------------------------------------------------------------------
__global__ void __launch_bounds__(256) kv_mma_kernel()
{
    __shared__ __nv_bfloat16 sA[3][64*72];
    __shared__ __nv_bfloat16 sB[3][72*72];
    const int blk = blockIdx.x;
    const int sp  = blk % KSPLIT;
    const int bh  = blk / KSPLIT;
    const int b = bh / HH, h = bh % HH;
    const int tid = threadIdx.x;
    const int wid = tid >> 5, lane = tid & 31;
    const int g = lane >> 2, t4 = lane & 3;
    const int wm = wid >> 2, wn = wid & 3;
    const int nt = (wn == 3) ? 3 : 2;

    const uint32_t suA[3] = {smem_u32(sA[0]), smem_u32(sA[1]), smem_u32(sA[2])};
    const uint32_t suB[3] = {smem_u32(sB[0]), smem_u32(sB[1]), smem_u32(sB[2])};

    for (int st = 0; st < 3; st++)
        for (int i = tid; i < 8*64; i += 256){
            int rr = i >> 6, cx = i & 63;
            sB[st][(64+rr)*72 + cx] = __float2bfloat16((rr == 0) ? 1.f : 0.f);
        }
    __syncthreads();

    float acc[2][3][4];
    #pragma unroll
    for (int i = 0; i < 2; i++)
        #pragma unroll
        for (int j = 0; j < 3; j++)
            #pragma unroll
            for (int e = 0; e < 4; e++) acc[i][j][e] = 0.f;

    const __nv_bfloat16* Kb = g_kt + ((size_t)b*CC + h*DD)*TT + sp*(TT/KSPLIT);
    const __nv_bfloat16* Vb = g_vt + ((size_t)b*CC + h*DD)*TT + sp*(TT/KSPLIT);

    auto load_stage = [&](int st, int tc){
        #pragma unroll
        for (int r = 0; r < 2; r++){
            int i = tid + r*256;
            int row = i >> 3, cq = i & 7;
            CP_ASYNC16(suA[st] + (uint32_t)(row*72 + cq*8)*2,
                       Kb + (size_t)row*TT + tc*64 + cq*8);
            CP_ASYNC16(suB[st] + (uint32_t)(row*72 + cq*8)*2,
                       Vb + (size_t)row*TT + tc*64 + cq*8);
        }
        CP_COMMIT();
    };

    const int NT = (TT/KSPLIT)/64;   // 8
    load_stage(0, 0);
    load_stage(1, 1);

    for (int tc = 0; tc < NT; tc++){
        if (tc + 1 < NT){ CP_WAIT1(); } else { CP_WAIT0(); }
        __syncthreads();
        if (tc + 2 < NT) load_stage((tc+2) % 3, tc+2);

        const __nv_bfloat16* pa = sA[tc % 3];
        const __nv_bfloat16* pb = sB[tc % 3];
        #pragma unroll
        for (int s = 0; s < 4; s++){
            const int kb = s*16 + 2*t4;
            uint32_t ar[2][4], br[3][2];
            #pragma unroll
            for (int mf = 0; mf < 2; mf++){
                int r0 = wm*32 + mf*16 + g;
                ar[mf][0] = lds32(pa +  r0   *72 + kb);
                ar[mf][1] = lds32(pa + (r0+8)*72 + kb);
                ar[mf][2] = lds32(pa +  r0   *72 + kb + 8);
                ar[mf][3] = lds32(pa + (r0+8)*72 + kb + 8);
            }
            #pragma unroll
            for (int nf = 0; nf < 3; nf++){
                if (nf < nt){
                    int c0 = (nf == 2) ? (64 + g) : (wn*16 + nf*8 + g);
                    br[nf][0] = lds32(pb + c0*72 + kb);
                    br[nf][1] = lds32(pb + c0*72 + kb + 8);
                }
            }
            #pragma unroll
            for (int mf = 0; mf < 2; mf++)
                #pragma unroll
                for (int nf = 0; nf < 3; nf++)
                    if (nf < nt) mma_bf16(acc[mf][nf], ar[mf], br[nf]);
        }
        __syncthreads();
    }

    float* dst = g_kvP[sp][bh];
    #pragma unroll
    for (int mf = 0; mf < 2; mf++){
        const int m0 = wm*32 + mf*16 + g;
        #pragma unroll
        for (int nf = 0; nf < 3; nf++){
            if (nf >= nt) continue;
            const int n0 = (nf == 2) ? (64 + 2*t4) : (wn*16 + nf*8 + 2*t4);
            dst[(n0  )*64 + m0    ] = acc[mf][nf][0];
            dst[(n0+1)*64 + m0    ] = acc[mf][nf][1];
            dst[(n0  )*64 + m0 + 8] = acc[mf][nf][2];
            dst[(n0+1)*64 + m0 + 8] = acc[mf][nf][3];
        }
    }
}

// ---------------------------------------------------------------------------
// reduce KSPLIT kv partials -> bf16 slab g_kv16[bh][72*64]
// ---------------------------------------------------------------------------
__global__ void __launch_bounds__(256) kv_reduce_kernel()
{
    const int bh = blockIdx.x;
    const int tid = threadIdx.x;
    for (int i = tid; i < 72*64; i += 256){
        float s = 0.f;
        #pragma unroll
        for (int sp = 0; sp < KSPLIT; sp++) s += g_kvP[sp][bh][i];
        g_kv16[(size_t)bh*72*64 + i] = __float2bfloat16_rn(s);
    }
}

// ---------------------------------------------------------------------------
// attn via MMA: per (bh, 128-t chunk): A = q[t][d], B = [kv;ksum][n][d]
// kv slab + q both loaded via cp.async under one wait.
// ---------------------------------------------------------------------------
__global__ void __launch_bounds__(256) attn_mma_kernel()
{
    __shared__ __nv_bfloat16 sQ[128*72];
    __shared__ __nv_bfloat16 sB[72*72];
    const int blk = blockIdx.x;
    const int tc  = blk % (TT/128);
    const int bh  = blk / (TT/128);
    const int b = bh / HH, h = bh % HH;
    const int tid = threadIdx.x;
    const int wid = tid >> 5, lane = tid & 31;
    const int g = lane >> 2, t4 = lane & 3;
    const uint32_t suQ = smem_u32(sQ);
    const uint32_t suB = smem_u32(sB);

    // B: kv slab (72 rows x 128B) via cp.async; dst rows stride 144B (16B-aligned)
    const __nv_bfloat16* kvsrc = g_kv16 + (size_t)bh*72*64;
    {
        int i = tid;                          // 576 chunks < 2*256... use 3 waves
        #pragma unroll
        for (int r = 0; r < 3; r++){
            int j = i + r*256;
            if (j < 576){
                int row = j >> 3, cq = j & 7;
                CP_ASYNC16(suB + (uint32_t)(row*72 + cq*8)*2, kvsrc + row*64 + cq*8);
            }
        }
    }
    // A: 128 q rows
    const __nv_bfloat16* Qb = g_q16 + (size_t)(b*TT + tc*128)*CC + h*DD;
    #pragma unroll
    for (int r = 0; r < 4; r++){
        int i = tid + r*256;
        int row = i >> 3, cq = i & 7;
        CP_ASYNC16(suQ + (uint32_t)(row*72 + cq*8)*2, Qb + (size_t)row*CC + cq*8);
    }
    CP_COMMIT(); CP_WAIT0();
    __syncthreads();

    float acc[9][4];
    #pragma unroll
    for (int i = 0; i < 9; i++)
        #pragma unroll
        for (int e = 0; e < 4; e++) acc[i][e] = 0.f;

    const int m0 = wid * 16;
    #pragma unroll
    for (int s = 0; s < 4; s++){
        const int kb = s*16 + 2*t4;
        uint32_t ar[4], br[9][2];
        ar[0] = lds32(sQ + (m0+g  )*72 + kb);
        ar[1] = lds32(sQ + (m0+g+8)*72 + kb);
        ar[2] = lds32(sQ + (m0+g  )*72 + kb + 8);
        ar[3] = lds32(sQ + (m0+g+8)*72 + kb + 8);
        #pragma unroll
        for (int nf = 0; nf < 9; nf++){
            int c0 = nf*8 + g;
            br[nf][0] = lds32(sB + c0*72 + kb);
            br[nf][1] = lds32(sB + c0*72 + kb + 8);
        }
        #pragma unroll
        for (int nf = 0; nf < 9; nf++)
            mma_bf16(acc[nf], ar, br[nf]);
    }

    float zlo = __shfl_sync(0xffffffffu, acc[8][0], lane & ~3);
    float zhi = __shfl_sync(0xffffffffu, acc[8][2], lane & ~3);
    const float rlo = 1.f / (zlo + 1e-6f);
    const float rhi = 1.f / (zhi + 1e-6f);

    const size_t row0 = (size_t)(b*TT + tc*128 + m0 + g);
    #pragma unroll
    for (int nf = 0; nf < 8; nf++){
        const int n0 = h*DD + nf*8 + 2*t4;
        *reinterpret_cast<__nv_bfloat162*>(g_attn16 +  row0     *CC + n0)
            = __floats2bfloat162_rn(acc[nf][0]*rlo, acc[nf][1]*rlo);
        *reinterpret_cast<__nv_bfloat162*>(g_attn16 + (row0 + 8)*CC + n0)
            = __floats2bfloat162_rn(acc[nf][2]*rhi, acc[nf][3]*rhi);
    }
}

// ---------------------------------------------------------------------------
extern "C" void kernel_launch(void* const* d_in, const int* in_sizes, int n_in,
                              void* d_out, int out_size)
{
    const float* x  = (const float*)d_in[0];
    const float* Wq = (const float*)d_in[1];
    const float* bq = (const float*)d_in[2];
    const float* Wk = (const float*)d_in[3];
    const float* bk = (const float*)d_in[4];
    const float* Wv = (const float*)d_in[5];
    const float* bv = (const float*)d_in[6];
    const float* Wo = (const float*)d_in[7];
    const float* bo = (const float*)d_in[8];
    float* out = (float*)d_out;

    __nv_bfloat16 *gxt, *gq, *gkt, *gvt, *gattn, *gw;
    cudaGetSymbolAddress((void**)&gxt,  g_xt);
    cudaGetSymbolAddress((void**)&gq,   g_q16);
    cudaGetSymbolAddress((void**)&gkt,  g_kt);
    cudaGetSymbolAddress((void**)&gvt,  g_vt);
    cudaGetSymbolAddress((void**)&gattn,g_attn16);
    cudaGetSymbolAddress((void**)&gw,   g_w16);

    cudaFuncSetAttribute(gemm_qkv, cudaFuncAttributeMaxDynamicSharedMemorySize, GEMM_SMEM);
    cudaFuncSetAttribute(gemm_out, cudaFuncAttributeMaxDynamicSharedMemorySize, GEMM_SMEM);

    // 1. pack inputs to bf16
    transpose_round_kernel<<<dim3(TT/64, CC/64, BB), 256>>>(x);
    round_w4_kernel<<<dim3(CC*CC/1024, 4), 256>>>(Wq, Wk, Wv, Wo, gw);

    // 2. Q/K/V projections merged, z-fastest for A-tile L2 reuse
    gemm_qkv<<<dim3(3, BT/128, CC/128), 256, GEMM_SMEM>>>(
        gxt, gw, bq, bk, bv, gq, gkt, gvt);

    // 3. linear attention (tensor cores)
    kv_mma_kernel<<<BB*HH*KSPLIT, 256>>>();
    kv_reduce_kernel<<<BB*HH, 256>>>();
    attn_mma_kernel<<<BB*HH*(TT/128), 256>>>();

    // 4. output projection, n-fastest for A-tile L2 reuse
    gemm_out<<<dim3(CC/128, BT/128), 256, GEMM_SMEM>>>(
        gattn, gw + 3*(size_t)CC*CC, bo, x, out);
}